// round 3
// baseline (speedup 1.0000x reference)
#include <cuda_runtime.h>
#include <cuda_fp16.h>

// Problem constants
#define BN   128    // batch
#define DN   512    // inputs = hidden = outputs = maxlen
#define TN   512    // timesteps
#define NCTA 128
#define NTHR 256

// ---------------- device scratch (allowed: __device__ globals) ----------------
__device__ __align__(16) float  d_xT[(size_t)TN * DN * BN];     // [t][m][b] = x[b][m][t]   (134 MB)
__device__ __align__(16) __half d_x16[(size_t)BN * DN * TN];    // fp16 copy of x, [b][m][t] (67 MB)
__device__ __align__(16) float  d_hT[2][DN * BN];               // double-buffered h, [j][b]
__device__ __align__(16) float  d_logitsT[DN * BN];             // [j][b]
__device__ __align__(16) float  d_appliedT[DN * BN];            // [t'][b]
__device__ __align__(16) float  d_gT[DN * BN];                  // [j][b]
__device__ unsigned d_bar_count;
__device__ unsigned d_bar_sense;

// ---------------- init kernels ----------------
__global__ void k_init() {
    int i = blockIdx.x * blockDim.x + threadIdx.x;
    if (i < DN * BN) d_hT[0][i] = 0.0f;
    if (i == 0) { d_bar_count = 0u; d_bar_sense = 0u; }
}

// transpose x[b][m][t] -> xT[t][m][b]
__global__ void k_transpose(const float* __restrict__ x) {
    __shared__ float tile[32][33];
    int t0 = blockIdx.x * 32;           // 16 blocks
    int b0 = blockIdx.y * 32;           // 4 blocks
    int m  = blockIdx.z;                // 512 blocks
    int tx = threadIdx.x & 31;
    int ty = threadIdx.x >> 5;          // 0..7
    #pragma unroll
    for (int r = 0; r < 32; r += 8)
        tile[ty + r][tx] = x[(size_t)(b0 + ty + r) * DN * TN + (size_t)m * TN + (t0 + tx)];
    __syncthreads();
    #pragma unroll
    for (int r = 0; r < 32; r += 8)
        d_xT[(size_t)(t0 + ty + r) * (DN * BN / DN * DN) /* = 65536 */ + (size_t)m * BN + (b0 + tx)]
            = tile[tx][ty + r];
}

// fp32 -> fp16 copy of x
__global__ void k_tohalf(const float* __restrict__ x) {
    const float2* x2 = (const float2*)x;
    __half2* o2 = (__half2*)d_x16;
    size_t n2 = (size_t)BN * DN * TN / 2;
    for (size_t i = (size_t)blockIdx.x * blockDim.x + threadIdx.x; i < n2;
         i += (size_t)gridDim.x * blockDim.x) {
        o2[i] = __float22half2_rn(x2[i]);
    }
}

// ---------------- grid barrier (128 co-resident CTAs) ----------------
__device__ __forceinline__ void gridbar(unsigned& epoch) {
    __syncthreads();
    if (threadIdx.x == 0) {
        epoch += NCTA;
        __threadfence();
        unsigned a = atomicAdd(&d_bar_count, 1u) + 1u;
        if (a == epoch) {
            atomicExch(&d_bar_sense, epoch);
        } else {
            while (*(volatile unsigned*)&d_bar_sense < epoch) { }
        }
        __threadfence();
    }
    __syncthreads();
}

// ---------------- warp reductions ----------------
__device__ __forceinline__ float warpMax(float v) {
    #pragma unroll
    for (int o = 16; o; o >>= 1) v = fmaxf(v, __shfl_xor_sync(0xffffffffu, v, o));
    return v;
}
__device__ __forceinline__ float warpSum(float v) {
    #pragma unroll
    for (int o = 16; o; o >>= 1) v += __shfl_xor_sync(0xffffffffu, v, o);
    return v;
}

// ---------------- N-partitioned GEMM stage: 4 output cols per CTA ----------------
// out[b][j] = sum_k act[b][k] * W[j][k] + bias[j];  act stored transposed [k][b].
// act0 covers k in [0,512), act1 covers k in [512, 1024) (if KT==16).
// mode: 0 = plain -> outT[j][b], 1 = relu -> outT[j][b], 2 = plain -> out[b][j] (row-major)
__device__ __forceinline__ void gemm4(
    const float* __restrict__ act0, const float* __restrict__ act1,
    const float* __restrict__ W, int KT, const float* __restrict__ bias,
    float* __restrict__ outp, int c, int mode, float* s_act, float* s_w)
{
    const int b  = threadIdx.x & 127;
    const int jj = threadIdx.x >> 7;     // 0..1
    const int j0 = c * 4 + jj * 2;
    const int Ktot = KT * 64;
    float acc0 = 0.0f, acc1 = 0.0f;
    for (int tile = 0; tile < KT; ++tile) {
        const int kbase = tile * 64;
        const float* src = (kbase < 512) ? (act0 + (size_t)kbase * BN)
                                         : (act1 + (size_t)(kbase - 512) * BN);
        __syncthreads();
        {   // load 64x128 activation tile (32 KB), coalesced float4
            const float4* s4 = (const float4*)src;
            float4* dst = (float4*)s_act;
            #pragma unroll
            for (int i = 0; i < 8; ++i) dst[threadIdx.x + i * NTHR] = s4[threadIdx.x + i * NTHR];
        }
        {   // 4 cols x 64 k weights = 256 floats, one per thread
            int i = threadIdx.x;
            int jc = i >> 6, k = i & 63;
            s_w[i] = W[(size_t)(c * 4 + jc) * Ktot + kbase + k];
        }
        __syncthreads();
        const float* wa = s_w + (jj * 2) * 64;
        const float* wb = wa + 64;
        #pragma unroll 16
        for (int k = 0; k < 64; ++k) {
            float a = s_act[k * BN + b];
            acc0 = fmaf(a, wa[k], acc0);
            acc1 = fmaf(a, wb[k], acc1);
        }
    }
    acc0 += bias[j0];
    acc1 += bias[j0 + 1];
    if (mode == 1) { acc0 = fmaxf(acc0, 0.0f); acc1 = fmaxf(acc1, 0.0f); }
    if (mode == 2) {
        outp[(size_t)b * DN + j0]     = acc0;
        outp[(size_t)b * DN + j0 + 1] = acc1;
    } else {
        outp[(size_t)j0 * BN + b]       = acc0;
        outp[(size_t)(j0 + 1) * BN + b] = acc1;
    }
}

// ---------------- stage B: softmax + einsum, CTA handles batch b ----------------
__device__ __forceinline__ void stageB(int b, float* s_vec, float* s_scr, float* s_red) {
    const int tid = threadIdx.x;
    // gather logits row b (512 values, 2 per thread)
    float l0 = d_logitsT[(size_t)tid * BN + b];
    float l1 = d_logitsT[(size_t)(tid + 256) * BN + b];
    float vmax = warpMax(fmaxf(l0, l1));
    if ((tid & 31) == 0) s_scr[tid >> 5] = vmax;
    __syncthreads();
    float M = s_scr[0];
    #pragma unroll
    for (int i = 1; i < 8; ++i) M = fmaxf(M, s_scr[i]);
    float e0 = __expf(l0 - M), e1 = __expf(l1 - M);
    float ws = warpSum(e0 + e1);
    __syncthreads();
    if ((tid & 31) == 0) s_scr[tid >> 5] = ws;
    __syncthreads();
    float S = 0.0f;
    #pragma unroll
    for (int i = 0; i < 8; ++i) S += s_scr[i];
    float inv = 1.0f / S;
    s_vec[tid] = e0 * inv;
    s_vec[tid + 256] = e1 * inv;
    __syncthreads();

    // einsum: applied[b][t'] = sum_m w[m] * x16[b][m][t']
    const int mq = tid >> 6;     // 0..3 : quarter of m
    const int tg = tid & 63;     // 8 t'-cols per thread
    float acc[8] = {0, 0, 0, 0, 0, 0, 0, 0};
    const __half* xb = d_x16 + (size_t)b * DN * TN;
    for (int mi = 0; mi < 128; ++mi) {
        int m_ = mq * 128 + mi;
        float w = s_vec[m_];
        uint4 v = *(const uint4*)(xb + (size_t)m_ * TN + tg * 8);
        const __half2* h2 = (const __half2*)&v;
        float2 f0 = __half22float2(h2[0]);
        float2 f1 = __half22float2(h2[1]);
        float2 f2 = __half22float2(h2[2]);
        float2 f3 = __half22float2(h2[3]);
        acc[0] = fmaf(w, f0.x, acc[0]); acc[1] = fmaf(w, f0.y, acc[1]);
        acc[2] = fmaf(w, f1.x, acc[2]); acc[3] = fmaf(w, f1.y, acc[3]);
        acc[4] = fmaf(w, f2.x, acc[4]); acc[5] = fmaf(w, f2.y, acc[5]);
        acc[6] = fmaf(w, f3.x, acc[6]); acc[7] = fmaf(w, f3.y, acc[7]);
    }
    #pragma unroll
    for (int q = 0; q < 8; ++q) s_red[mq * DN + tg * 8 + q] = acc[q];
    __syncthreads();
    for (int col = tid; col < DN; col += NTHR) {
        float v = s_red[col] + s_red[DN + col] + s_red[2 * DN + col] + s_red[3 * DN + col];
        d_appliedT[(size_t)col * BN + b] = v;
    }
}

// ---------------- stage D: gi/gh GEMMs + GRU, CTA owns 4 hidden cols ----------------
__device__ __forceinline__ void stageD(
    const float* __restrict__ hTold, float* __restrict__ hTnew,
    const float* __restrict__ w_ih, const float* __restrict__ w_hh,
    const float* __restrict__ b_ih, const float* __restrict__ b_hh,
    int c, float* s_act, float* s_w)
{
    const int b  = threadIdx.x & 127;
    const int jj = threadIdx.x >> 7;
    const int j0 = c * 4 + jj * 2;
    float gi[6] = {0, 0, 0, 0, 0, 0};   // [gate*2 + col]
    float gh[6] = {0, 0, 0, 0, 0, 0};
    for (int pass = 0; pass < 2; ++pass) {
        const float* act = pass ? hTold : d_gT;
        const float* W   = pass ? w_hh : w_ih;
        float* acc = pass ? gh : gi;
        for (int tile = 0; tile < 8; ++tile) {
            __syncthreads();
            {
                const float4* s4 = (const float4*)(act + (size_t)tile * 64 * BN);
                float4* dst = (float4*)s_act;
                #pragma unroll
                for (int i = 0; i < 8; ++i) dst[threadIdx.x + i * NTHR] = s4[threadIdx.x + i * NTHR];
            }
            // 3 gates x 4 cols x 64 k = 768 floats
            for (int i = threadIdx.x; i < 768; i += NTHR) {
                int gjc = i >> 6, k = i & 63;
                int gate = gjc >> 2, jc = gjc & 3;
                s_w[i] = W[(size_t)(gate * DN + c * 4 + jc) * DN + tile * 64 + k];
            }
            __syncthreads();
            const int o0 = (jj * 2) * 64;
            #pragma unroll 8
            for (int k = 0; k < 64; ++k) {
                float a = s_act[k * BN + b];
                acc[0] = fmaf(a, s_w[o0 + k],            acc[0]);
                acc[1] = fmaf(a, s_w[o0 + 64 + k],       acc[1]);
                acc[2] = fmaf(a, s_w[o0 + 256 + k],      acc[2]);
                acc[3] = fmaf(a, s_w[o0 + 320 + k],      acc[3]);
                acc[4] = fmaf(a, s_w[o0 + 512 + k],      acc[4]);
                acc[5] = fmaf(a, s_w[o0 + 576 + k],      acc[5]);
            }
        }
    }
    #pragma unroll
    for (int cc = 0; cc < 2; ++cc) {
        int j = j0 + cc;
        float ir = gi[0 + cc] + b_ih[j];
        float iz = gi[2 + cc] + b_ih[DN + j];
        float in_ = gi[4 + cc] + b_ih[2 * DN + j];
        float hr = gh[0 + cc] + b_hh[j];
        float hz = gh[2 + cc] + b_hh[DN + j];
        float hn = gh[4 + cc] + b_hh[2 * DN + j];
        float r = 1.0f / (1.0f + __expf(-(ir + hr)));
        float z = 1.0f / (1.0f + __expf(-(iz + hz)));
        float n = tanhf(in_ + r * hn);
        float hold = hTold[(size_t)j * BN + b];
        hTnew[(size_t)j * BN + b] = (1.0f - z) * n + z * hold;
    }
}

// ---------------- persistent kernel ----------------
__global__ void __launch_bounds__(NTHR, 1) rnn_persistent(
    const float* __restrict__ x,
    const float* __restrict__ attn_W, const float* __restrict__ attn_b,
    const float* __restrict__ comb_W, const float* __restrict__ comb_b,
    const float* __restrict__ w_ih, const float* __restrict__ w_hh,
    const float* __restrict__ b_ih, const float* __restrict__ b_hh,
    const float* __restrict__ out_W, const float* __restrict__ out_b,
    float* __restrict__ out)
{
    __shared__ float s_act[64 * BN];      // 32 KB (also reused as reduce buffer in stage B)
    __shared__ float s_w[12 * 64];        // 3 KB
    __shared__ float s_vec[DN + 64];      // softmax weights + scratch

    const int c = blockIdx.x;             // 0..127
    unsigned epoch = 0;

    for (int t = 0; t < TN; ++t) {
        const float* hOld = d_hT[t & 1];
        float* hNew = d_hT[(t + 1) & 1];
        const float* inpT = d_xT + (size_t)t * (DN * BN / DN * DN); // t * 65536

        // A: logits = [inp | h] @ attn_W.T + attn_b
        gemm4(inpT, hOld, attn_W, 16, attn_b, d_logitsT, c, 0, s_act, s_w);
        gridbar(epoch);
        // B: softmax + einsum
        stageB(c, s_vec, s_vec + DN, s_act);
        gridbar(epoch);
        // C: g = relu([inp | applied] @ comb_W.T + comb_b)
        gemm4(inpT, d_appliedT, comb_W, 16, comb_b, d_gT, c, 1, s_act, s_w);
        gridbar(epoch);
        // D: gi/gh GEMMs + GRU -> hNew
        stageD(hOld, hNew, w_ih, w_hh, b_ih, b_hh, c, s_act, s_w);
        gridbar(epoch);
    }
    // final: out = h @ out_W.T + out_b ; final h is in buffer 0
    gemm4(d_hT[0], d_hT[0], out_W, 8, out_b, out, c, 2, s_act, s_w);
}

// ---------------- launch ----------------
extern "C" void kernel_launch(void* const* d_in, const int* in_sizes, int n_in,
                              void* d_out, int out_size) {
    (void)in_sizes; (void)n_in; (void)out_size;
    const float* x      = (const float*)d_in[0];
    const float* attn_W = (const float*)d_in[1];
    const float* attn_b = (const float*)d_in[2];
    const float* comb_W = (const float*)d_in[3];
    const float* comb_b = (const float*)d_in[4];
    const float* w_ih   = (const float*)d_in[5];
    const float* w_hh   = (const float*)d_in[6];
    const float* b_ih   = (const float*)d_in[7];
    const float* b_hh   = (const float*)d_in[8];
    const float* out_W  = (const float*)d_in[9];
    const float* out_b  = (const float*)d_in[10];
    float* out = (float*)d_out;

    k_init<<<(DN * BN + NTHR - 1) / NTHR, NTHR>>>();
    k_transpose<<<dim3(16, 4, 512), NTHR>>>(x);
    k_tohalf<<<4096, NTHR>>>(x);
    rnn_persistent<<<NCTA, NTHR>>>(x, attn_W, attn_b, comb_W, comb_b,
                                   w_ih, w_hh, b_ih, b_hh, out_W, out_b, out);
}

// round 4
// speedup vs baseline: 2.0843x; 2.0843x over previous
#include <cuda_runtime.h>
#include <cuda_fp16.h>
#include <cstdint>

#define BN   128
#define DN   512
#define TN   512
#define NCTA 128
#define NTHR 256
#define HSZ  (BN * DN)   // 65536

// ---------------- device scratch ----------------
__device__ __align__(16) __half d_x16[(size_t)BN * DN * TN];   // [b][m][t]  (einsum operand)
__device__ __align__(16) __half d_xbm[(size_t)TN * BN * DN];   // [t][b][m]  (GEMM A operand)
__device__ __align__(16) __half d_wA[DN * 2 * DN];             // attn_W fp16 [512][1024]
__device__ __align__(16) __half d_wC[DN * 2 * DN];             // comb_W fp16 [512][1024]
__device__ __align__(16) __half d_wI[3 * DN * DN];             // w_ih fp16 [1536][512]
__device__ __align__(16) __half d_wH[3 * DN * DN];             // w_hh fp16 [1536][512]
__device__ __align__(16) __half d_wO[DN * DN];                 // out_W fp16 [512][512]
__device__ __align__(16) float  d_logits[HSZ];                 // [b][j] fp32
__device__ __align__(16) __half d_g16[HSZ];                    // [b][j]
__device__ __align__(16) __half d_ap16[HSZ];                   // [b][t']
__device__ __align__(16) float  d_h32[2][HSZ];                 // [b][j]
__device__ __align__(16) __half d_h16[2][HSZ];                 // [b][j]
__device__ unsigned d_bar_count;
__device__ unsigned d_bar_sense;

// ---------------- init kernels ----------------
__global__ void k_init() {
    int i = blockIdx.x * blockDim.x + threadIdx.x;
    if (i < HSZ) { d_h32[0][i] = 0.0f; d_h16[0][i] = __float2half(0.0f); }
    if (i == 0) { d_bar_count = 0u; d_bar_sense = 0u; }
}

// x16[b][m][t] = (half)x[b][m][t]
__global__ void k_x16(const float* __restrict__ x) {
    size_t n = (size_t)BN * DN * TN;
    for (size_t i = (size_t)blockIdx.x * blockDim.x + threadIdx.x; i < n;
         i += (size_t)gridDim.x * blockDim.x)
        d_x16[i] = __float2half(x[i]);
}

// xbm[t][b][m] = (half)x[b][m][t]
__global__ void k_xbm(const float* __restrict__ x) {
    __shared__ float tile[32][33];
    int m0 = blockIdx.x * 32;  // 16
    int t0 = blockIdx.y * 32;  // 16
    int b  = blockIdx.z;       // 128
    int tx = threadIdx.x & 31;
    int ty = threadIdx.x >> 5;
    #pragma unroll
    for (int r = 0; r < 32; r += 8)
        tile[ty + r][tx] = x[(size_t)b * DN * TN + (size_t)(m0 + ty + r) * TN + (t0 + tx)];
    __syncthreads();
    #pragma unroll
    for (int r = 0; r < 32; r += 8)
        d_xbm[(size_t)(t0 + ty + r) * HSZ + (size_t)b * DN + (m0 + tx)]
            = __float2half(tile[tx][ty + r]);
}

// convert all weights to fp16 (single launch covers the largest)
__global__ void k_wconv(const float* __restrict__ aW, const float* __restrict__ cW,
                        const float* __restrict__ wi, const float* __restrict__ wh,
                        const float* __restrict__ oW) {
    int i = blockIdx.x * blockDim.x + threadIdx.x;
    if (i < DN * 2 * DN) { d_wA[i] = __float2half(aW[i]); d_wC[i] = __float2half(cW[i]); }
    if (i < 3 * DN * DN) { d_wI[i] = __float2half(wi[i]); d_wH[i] = __float2half(wh[i]); }
    if (i < DN * DN)     { d_wO[i] = __float2half(oW[i]); }
}

// ---------------- grid barrier (128 co-resident CTAs) ----------------
__device__ __forceinline__ void gridbar(unsigned& epoch) {
    __syncthreads();
    if (threadIdx.x == 0) {
        epoch += NCTA;
        __threadfence();
        unsigned a = atomicAdd(&d_bar_count, 1u) + 1u;
        if (a == epoch) {
            atomicExch(&d_bar_sense, epoch);
        } else {
            while (*(volatile unsigned*)&d_bar_sense < epoch) { }
        }
        __threadfence();
    }
    __syncthreads();
}

// ---------------- warp reductions ----------------
__device__ __forceinline__ float warpMax(float v) {
    #pragma unroll
    for (int o = 16; o; o >>= 1) v = fmaxf(v, __shfl_xor_sync(0xffffffffu, v, o));
    return v;
}
__device__ __forceinline__ float warpSum(float v) {
    #pragma unroll
    for (int o = 16; o; o >>= 1) v += __shfl_xor_sync(0xffffffffu, v, o);
    return v;
}

// ---------------- mma helpers ----------------
__device__ __forceinline__ void mma16816(float c[4], uint32_t a0, uint32_t a1,
                                         uint32_t a2, uint32_t a3,
                                         uint32_t b0, uint32_t b1) {
    asm volatile(
        "mma.sync.aligned.m16n8k16.row.col.f32.f16.f16.f32 "
        "{%0,%1,%2,%3}, {%4,%5,%6,%7}, {%8,%9}, {%0,%1,%2,%3};"
        : "+f"(c[0]), "+f"(c[1]), "+f"(c[2]), "+f"(c[3])
        : "r"(a0), "r"(a1), "r"(a2), "r"(a3), "r"(b0), "r"(b1));
}

// A fragment: act [b][k] row-major fp16, row stride DN. Tile rows row0..row0+15, k..k+15.
__device__ __forceinline__ void ldA(const __half* __restrict__ base, int row0, int k,
                                    uint32_t A[4]) {
    const int lane = threadIdx.x & 31;
    const int g = lane >> 2, tig = lane & 3;
    const __half* p0 = base + (size_t)(row0 + g) * DN + k + tig * 2;
    const __half* p1 = p0 + 8 * DN;
    A[0] = *(const uint32_t*)p0;
    A[1] = *(const uint32_t*)p1;
    A[2] = *(const uint32_t*)(p0 + 8);
    A[3] = *(const uint32_t*)(p1 + 8);
}

// B fragment: W [j][k] row-major fp16, row stride `stride`. Tile rows j0..j0+7, k..k+15.
__device__ __forceinline__ void ldB(const __half* __restrict__ W, int stride, int j0, int k,
                                    uint32_t Bf[2]) {
    const int lane = threadIdx.x & 31;
    const int g = lane >> 2, tig = lane & 3;
    const __half* p = W + (size_t)(j0 + g) * stride + k + tig * 2;
    Bf[0] = *(const uint32_t*)p;
    Bf[1] = *(const uint32_t*)(p + 8);
}

// ---------------- N-stage GEMM (stages A, C, out) ----------------
// out[b][j] = sum_k act[b][k] * W[j][k] (+bias). K split in 2 halves across warp
// pairs: base0 covers k_local in [0,KH) (W k-offset 0), base1 covers [KH,2*KH).
// CTA tile: M=16 (mt = cta>>4), N=32 (ng = cta&15); warp: nt = warp&3, kh = warp>>2.
// mode 0: fp32 out, mode 1: relu + fp16 out.
__device__ __forceinline__ void mma_nstage(
    const __half* __restrict__ base0, const __half* __restrict__ base1,
    const __half* __restrict__ W, int Wstride, int KH,
    const float* __restrict__ bias, int mode,
    float* __restrict__ out32, __half* __restrict__ out16, float* s_red)
{
    const int cta  = blockIdx.x;
    const int warp = threadIdx.x >> 5;
    const int lane = threadIdx.x & 31;
    const int mt = cta >> 4;            // 0..7
    const int ng = cta & 15;            // 0..15
    const int nt = warp & 3, kh = warp >> 2;
    const int b0 = mt * 16;
    const int j0 = ng * 32 + nt * 8;
    const __half* act = kh ? base1 : base0;
    const int kw0 = kh * KH;
    float c[4] = {0.f, 0.f, 0.f, 0.f};
    #pragma unroll 2
    for (int k = 0; k < KH; k += 16) {
        uint32_t A[4], Bf[2];
        ldA(act, b0, k, A);
        ldB(W, Wstride, j0, kw0 + k, Bf);
        mma16816(c, A[0], A[1], A[2], A[3], Bf[0], Bf[1]);
    }
    if (kh) {
        float* p = s_red + (warp - 4) * 128 + lane * 4;
        p[0] = c[0]; p[1] = c[1]; p[2] = c[2]; p[3] = c[3];
    }
    __syncthreads();
    if (!kh) {
        const float* p = s_red + warp * 128 + lane * 4;
        c[0] += p[0]; c[1] += p[1]; c[2] += p[2]; c[3] += p[3];
        const int g = lane >> 2, tig = lane & 3;
        const int j = j0 + tig * 2;
        const float bz0 = bias[j], bz1 = bias[j + 1];
        if (mode == 1) {
            float v0 = fmaxf(c[0] + bz0, 0.f), v1 = fmaxf(c[1] + bz1, 0.f);
            float v2 = fmaxf(c[2] + bz0, 0.f), v3 = fmaxf(c[3] + bz1, 0.f);
            *(__half2*)(out16 + (size_t)(b0 + g) * DN + j)     = __floats2half2_rn(v0, v1);
            *(__half2*)(out16 + (size_t)(b0 + g + 8) * DN + j) = __floats2half2_rn(v2, v3);
        } else {
            *(float2*)(out32 + (size_t)(b0 + g) * DN + j)     = make_float2(c[0] + bz0, c[1] + bz1);
            *(float2*)(out32 + (size_t)(b0 + g + 8) * DN + j) = make_float2(c[2] + bz0, c[3] + bz1);
        }
    }
}

// ---------------- stage B: softmax + einsum, CTA = batch b ----------------
__device__ __forceinline__ void stageB(float* s_vec, float* s_scr, float* s_red) {
    const int b = blockIdx.x;
    const int tid = threadIdx.x;
    float2 l = *(const float2*)(d_logits + (size_t)b * DN + tid * 2);
    float vmax = warpMax(fmaxf(l.x, l.y));
    if ((tid & 31) == 0) s_scr[tid >> 5] = vmax;
    __syncthreads();
    float M = s_scr[0];
    #pragma unroll
    for (int i = 1; i < 8; ++i) M = fmaxf(M, s_scr[i]);
    float e0 = __expf(l.x - M), e1 = __expf(l.y - M);
    float ws = warpSum(e0 + e1);
    __syncthreads();
    if ((tid & 31) == 0) s_scr[tid >> 5] = ws;
    __syncthreads();
    float S = 0.f;
    #pragma unroll
    for (int i = 0; i < 8; ++i) S += s_scr[i];
    float inv = 1.0f / S;
    s_vec[tid * 2]     = e0 * inv;
    s_vec[tid * 2 + 1] = e1 * inv;
    __syncthreads();
    // applied[b][t'] = sum_m w[m] * x16[b][m][t']
    const int mq = tid >> 6;     // quarter of m
    const int tg = tid & 63;     // 8 t' cols per thread
    float acc[8] = {0, 0, 0, 0, 0, 0, 0, 0};
    const __half* xb = d_x16 + (size_t)b * DN * TN;
    for (int mi = 0; mi < 128; ++mi) {
        int m_ = mq * 128 + mi;
        float w = s_vec[m_];
        uint4 v = *(const uint4*)(xb + (size_t)m_ * TN + tg * 8);
        const __half2* h2 = (const __half2*)&v;
        float2 f0 = __half22float2(h2[0]);
        float2 f1 = __half22float2(h2[1]);
        float2 f2 = __half22float2(h2[2]);
        float2 f3 = __half22float2(h2[3]);
        acc[0] = fmaf(w, f0.x, acc[0]); acc[1] = fmaf(w, f0.y, acc[1]);
        acc[2] = fmaf(w, f1.x, acc[2]); acc[3] = fmaf(w, f1.y, acc[3]);
        acc[4] = fmaf(w, f2.x, acc[4]); acc[5] = fmaf(w, f2.y, acc[5]);
        acc[6] = fmaf(w, f3.x, acc[6]); acc[7] = fmaf(w, f3.y, acc[7]);
    }
    #pragma unroll
    for (int q = 0; q < 8; ++q) s_red[mq * DN + tg * 8 + q] = acc[q];
    __syncthreads();
    for (int col = tid; col < DN; col += NTHR) {
        float v = s_red[col] + s_red[DN + col] + s_red[2 * DN + col] + s_red[3 * DN + col];
        d_ap16[(size_t)b * DN + col] = __float2half(v);
    }
}

// ---------------- stage D: gi/gh mma + GRU ----------------
// Global warp id w = cta*8+warp decomposed bijectively: jt = w>>4 (j0=jt*8),
// mt = (w>>1)&7 (b0=mt*16), kh = w&1 (K half). Partner = warp^1 (same CTA).
__device__ __forceinline__ void stageD(
    const __half* __restrict__ g16, const __half* __restrict__ h16o,
    const float* __restrict__ h32o, float* __restrict__ h32n, __half* __restrict__ h16n,
    const float* __restrict__ b_ih, const float* __restrict__ b_hh, float* s_red)
{
    const int cta  = blockIdx.x;
    const int warp = threadIdx.x >> 5;
    const int lane = threadIdx.x & 31;
    const int w  = cta * 8 + warp;
    const int jt = w >> 4;            // 0..63
    const int mt = (w >> 1) & 7;      // 0..7
    const int kh = w & 1;
    const int b0 = mt * 16;
    const int j0 = jt * 8;
    const int k0 = kh * 256;
    float cI[3][4] = {};
    float cH[3][4] = {};
    #pragma unroll 2
    for (int k = 0; k < 256; k += 16) {
        uint32_t Ag[4], Ah[4], Bf[2];
        ldA(g16,  b0, k0 + k, Ag);
        ldA(h16o, b0, k0 + k, Ah);
        #pragma unroll
        for (int gate = 0; gate < 3; ++gate) {
            ldB(d_wI, DN, gate * DN + j0, k0 + k, Bf);
            mma16816(cI[gate], Ag[0], Ag[1], Ag[2], Ag[3], Bf[0], Bf[1]);
            ldB(d_wH, DN, gate * DN + j0, k0 + k, Bf);
            mma16816(cH[gate], Ah[0], Ah[1], Ah[2], Ah[3], Bf[0], Bf[1]);
        }
    }
    if (kh) {
        float* p = s_red + (warp >> 1) * 768 + lane * 24;
        #pragma unroll
        for (int gg = 0; gg < 3; ++gg)
            #pragma unroll
            for (int i = 0; i < 4; ++i) { p[gg * 4 + i] = cI[gg][i]; p[12 + gg * 4 + i] = cH[gg][i]; }
    }
    __syncthreads();
    if (!kh) {
        const float* p = s_red + (warp >> 1) * 768 + lane * 24;
        #pragma unroll
        for (int gg = 0; gg < 3; ++gg)
            #pragma unroll
            for (int i = 0; i < 4; ++i) { cI[gg][i] += p[gg * 4 + i]; cH[gg][i] += p[12 + gg * 4 + i]; }
        const int g = lane >> 2, tig = lane & 3;
        #pragma unroll
        for (int hi = 0; hi < 2; ++hi) {
            const int b = b0 + g + hi * 8;
            float hv[2];
            #pragma unroll
            for (int cc = 0; cc < 2; ++cc) {
                const int j = j0 + tig * 2 + cc;
                const int ri = hi * 2 + cc;
                float ir  = cI[0][ri] + b_ih[j];
                float iz  = cI[1][ri] + b_ih[DN + j];
                float in_ = cI[2][ri] + b_ih[2 * DN + j];
                float hr  = cH[0][ri] + b_hh[j];
                float hz  = cH[1][ri] + b_hh[DN + j];
                float hn  = cH[2][ri] + b_hh[2 * DN + j];
                float r = 1.0f / (1.0f + __expf(-(ir + hr)));
                float z = 1.0f / (1.0f + __expf(-(iz + hz)));
                float n = tanhf(in_ + r * hn);
                float hold = h32o[(size_t)b * DN + j];
                float hnew = (1.0f - z) * n + z * hold;
                h32n[(size_t)b * DN + j] = hnew;
                hv[cc] = hnew;
            }
            *(__half2*)(h16n + (size_t)b * DN + j0 + tig * 2) = __floats2half2_rn(hv[0], hv[1]);
        }
    }
}

// ---------------- persistent kernel ----------------
__global__ void __launch_bounds__(NTHR, 1) rnn_mma(
    const float* __restrict__ attn_b, const float* __restrict__ comb_b,
    const float* __restrict__ b_ih, const float* __restrict__ b_hh,
    const float* __restrict__ out_b, float* __restrict__ out)
{
    __shared__ float s_red[3072];   // 12 KB (reduction scratch, einsum partials)
    __shared__ float s_vec[DN];     // softmax weights
    __shared__ float s_scr[8];

    unsigned epoch = 0;
    for (int t = 0; t < TN; ++t) {
        const __half* xin  = d_xbm + (size_t)t * HSZ;
        const __half* h16o = d_h16[t & 1];
        // A: logits = [inp | h] @ attn_W.T + attn_b   (fp32 out)
        mma_nstage(xin, h16o, d_wA, 2 * DN, 512, attn_b, 0, d_logits, nullptr, s_red);
        gridbar(epoch);
        // B: softmax + einsum -> ap16
        stageB(s_vec, s_scr, s_red);
        gridbar(epoch);
        // C: g = relu([inp | applied] @ comb_W.T + comb_b)  (fp16 out)
        mma_nstage(xin, d_ap16, d_wC, 2 * DN, 512, comb_b, 1, nullptr, d_g16, s_red);
        gridbar(epoch);
        // D: GRU
        stageD(d_g16, h16o, d_h32[t & 1], d_h32[(t + 1) & 1], d_h16[(t + 1) & 1],
               b_ih, b_hh, s_red);
        gridbar(epoch);
    }
    // out = h_final @ out_W.T + out_b ; final h16 is buffer 0, K=512 split 256/256
    mma_nstage(d_h16[0], d_h16[0] + 256, d_wO, DN, 256, out_b, 0, out, nullptr, s_red);
}

// ---------------- launch ----------------
extern "C" void kernel_launch(void* const* d_in, const int* in_sizes, int n_in,
                              void* d_out, int out_size) {
    (void)in_sizes; (void)n_in; (void)out_size;
    const float* x      = (const float*)d_in[0];
    const float* attn_W = (const float*)d_in[1];
    const float* attn_b = (const float*)d_in[2];
    const float* comb_W = (const float*)d_in[3];
    const float* comb_b = (const float*)d_in[4];
    const float* w_ih   = (const float*)d_in[5];
    const float* w_hh   = (const float*)d_in[6];
    const float* b_ih   = (const float*)d_in[7];
    const float* b_hh   = (const float*)d_in[8];
    const float* out_W  = (const float*)d_in[9];
    const float* out_b  = (const float*)d_in[10];
    float* out = (float*)d_out;

    k_init<<<(HSZ + NTHR - 1) / NTHR, NTHR>>>();
    k_x16<<<2048, NTHR>>>(x);
    k_xbm<<<dim3(16, 16, 128), NTHR>>>(x);
    k_wconv<<<(3 * DN * DN + NTHR - 1) / NTHR, NTHR>>>(attn_W, comb_W, w_ih, w_hh, out_W);
    rnn_mma<<<NCTA, NTHR>>>(attn_b, comb_b, b_ih, b_hh, out_b, out);
}

// round 5
// speedup vs baseline: 3.5591x; 1.7076x over previous
#include <cuda_runtime.h>
#include <cuda_fp16.h>
#include <cstdint>

#define BN   128
#define DN   512
#define TN   512
#define NCTA 128
#define NTHR 512
#define HSZ  (BN * DN)   // 65536

// padded smem row strides (halves): +8 halves = 16B shift per row -> conflict-free
#define DN2P 1032   // for 1024-wide rows
#define DKP  520    // for 512-wide rows

// dynamic smem byte offsets
#define OFF_WA   0                       // 32 x 1032 halves = 66048 B
#define OFF_WC   66048                   // 66048 B
#define OFF_WIH  132096                  // 48 x 520 halves  = 49920 B
#define OFF_R    182016                  // scratch union    = 40960 B
#define OFF_VEC  222976                  // 512 floats       = 2048 B
#define OFF_SCR  225024                  // 16 floats        = 64 B
#define SMEM_TOTAL 225088

// ---------------- device scratch ----------------
__device__ __align__(16) __half d_x16[(size_t)BN * DN * TN];   // [b][m][t]  einsum operand
__device__ __align__(16) __half d_xbm[(size_t)TN * BN * DN];   // [t][b][m]  GEMM A operand
__device__ __align__(16) __half d_wA[DN * 2 * DN];             // attn_W fp16 [512][1024]
__device__ __align__(16) __half d_wC[DN * 2 * DN];             // comb_W fp16 [512][1024]
__device__ __align__(16) __half d_wI[3 * DN * DN];             // w_ih fp16 [1536][512]
__device__ __align__(16) __half d_wH[3 * DN * DN];             // w_hh fp16 [1536][512]
__device__ __align__(16) __half d_wO[DN * DN];                 // out_W fp16 [512][512]
__device__ __align__(16) float  d_logits[HSZ];                 // [b][j]
__device__ __align__(16) __half d_g16[HSZ];                    // [b][j]
__device__ __align__(16) __half d_ap16[HSZ];                   // [b][t']
__device__ __align__(16) float  d_h32[2][HSZ];                 // [b][j]
__device__ __align__(16) __half d_h16[2][HSZ];                 // [b][j]
__device__ unsigned d_bar_count;
__device__ unsigned d_bar_sense;

// ---------------- init kernels ----------------
__global__ void k_init() {
    int i = blockIdx.x * blockDim.x + threadIdx.x;
    if (i < HSZ) { d_h32[0][i] = 0.0f; d_h16[0][i] = __float2half(0.0f); }
    if (i == 0) { d_bar_count = 0u; d_bar_sense = 0u; }
}

__global__ void k_x16(const float* __restrict__ x) {
    size_t n = (size_t)BN * DN * TN;
    for (size_t i = (size_t)blockIdx.x * blockDim.x + threadIdx.x; i < n;
         i += (size_t)gridDim.x * blockDim.x)
        d_x16[i] = __float2half(x[i]);
}

// xbm[t][b][m] = (half)x[b][m][t]
__global__ void k_xbm(const float* __restrict__ x) {
    __shared__ float tile[32][33];
    int m0 = blockIdx.x * 32;
    int t0 = blockIdx.y * 32;
    int b  = blockIdx.z;
    int tx = threadIdx.x & 31;
    int ty = threadIdx.x >> 5;
    #pragma unroll
    for (int r = 0; r < 32; r += 8)
        tile[ty + r][tx] = x[(size_t)b * DN * TN + (size_t)(m0 + ty + r) * TN + (t0 + tx)];
    __syncthreads();
    #pragma unroll
    for (int r = 0; r < 32; r += 8)
        d_xbm[(size_t)(t0 + ty + r) * HSZ + (size_t)b * DN + (m0 + tx)]
            = __float2half(tile[tx][ty + r]);
}

__global__ void k_wconv(const float* __restrict__ aW, const float* __restrict__ cW,
                        const float* __restrict__ wi, const float* __restrict__ wh,
                        const float* __restrict__ oW) {
    int i = blockIdx.x * blockDim.x + threadIdx.x;
    if (i < DN * 2 * DN) { d_wA[i] = __float2half(aW[i]); d_wC[i] = __float2half(cW[i]); }
    if (i < 3 * DN * DN) { d_wI[i] = __float2half(wi[i]); d_wH[i] = __float2half(wh[i]); }
    if (i < DN * DN)     { d_wO[i] = __float2half(oW[i]); }
}

// ---------------- grid barrier ----------------
__device__ __forceinline__ void gridbar(unsigned& epoch) {
    __syncthreads();
    if (threadIdx.x == 0) {
        epoch += NCTA;
        __threadfence();
        unsigned a = atomicAdd(&d_bar_count, 1u) + 1u;
        if (a == epoch) {
            atomicExch(&d_bar_sense, epoch);
        } else {
            while (*(volatile unsigned*)&d_bar_sense < epoch) { }
        }
        __threadfence();
    }
    __syncthreads();
}

// ---------------- warp reductions ----------------
__device__ __forceinline__ float warpMax(float v) {
    #pragma unroll
    for (int o = 16; o; o >>= 1) v = fmaxf(v, __shfl_xor_sync(0xffffffffu, v, o));
    return v;
}
__device__ __forceinline__ float warpSum(float v) {
    #pragma unroll
    for (int o = 16; o; o >>= 1) v += __shfl_xor_sync(0xffffffffu, v, o);
    return v;
}

// ---------------- mma helpers ----------------
__device__ __forceinline__ void mma16816(float c[4], uint32_t a0, uint32_t a1,
                                         uint32_t a2, uint32_t a3,
                                         uint32_t b0, uint32_t b1) {
    asm volatile(
        "mma.sync.aligned.m16n8k16.row.col.f32.f16.f16.f32 "
        "{%0,%1,%2,%3}, {%4,%5,%6,%7}, {%8,%9}, {%0,%1,%2,%3};"
        : "+f"(c[0]), "+f"(c[1]), "+f"(c[2]), "+f"(c[3])
        : "r"(a0), "r"(a1), "r"(a2), "r"(a3), "r"(b0), "r"(b1));
}

// A fragment from GLOBAL act [b][k], row stride DN
__device__ __forceinline__ void ldA(const __half* __restrict__ base, int row0, int k,
                                    uint32_t A[4]) {
    const int lane = threadIdx.x & 31;
    const int g = lane >> 2, tig = lane & 3;
    const __half* p0 = base + (size_t)(row0 + g) * DN + k + tig * 2;
    const __half* p1 = p0 + 8 * DN;
    A[0] = *(const uint32_t*)p0;
    A[1] = *(const uint32_t*)p1;
    A[2] = *(const uint32_t*)(p0 + 8);
    A[3] = *(const uint32_t*)(p1 + 8);
}

// B fragment from GLOBAL W [j][k], row stride `stride`
__device__ __forceinline__ void ldB(const __half* __restrict__ W, int stride, int j0, int k,
                                    uint32_t Bf[2]) {
    const int lane = threadIdx.x & 31;
    const int g = lane >> 2, tig = lane & 3;
    const __half* p = W + (size_t)(j0 + g) * stride + k + tig * 2;
    Bf[0] = *(const uint32_t*)p;
    Bf[1] = *(const uint32_t*)(p + 8);
}

// A fragment from SMEM tile, padded row stride `stridep` (halves)
__device__ __forceinline__ void ldAs(const __half* s, int stridep, int k, uint32_t A[4]) {
    const int lane = threadIdx.x & 31;
    const int g = lane >> 2, tig = lane & 3;
    const __half* p0 = s + g * stridep + k + tig * 2;
    const __half* p1 = p0 + 8 * stridep;
    A[0] = *(const uint32_t*)p0;
    A[1] = *(const uint32_t*)p1;
    A[2] = *(const uint32_t*)(p0 + 8);
    A[3] = *(const uint32_t*)(p1 + 8);
}

// B fragment from SMEM weights, padded row stride
__device__ __forceinline__ void ldBs(const __half* s, int stridep, int row0, int k,
                                     uint32_t Bf[2]) {
    const int lane = threadIdx.x & 31;
    const int g = lane >> 2, tig = lane & 3;
    const __half* p = s + (row0 + g) * stridep + k + tig * 2;
    Bf[0] = *(const uint32_t*)p;
    Bf[1] = *(const uint32_t*)(p + 8);
}

// ---------------- stages A / C: out[b][j] = act(..) ; weights in smem ----------------
// CTA: b-tile = (cta>>4)*16 (16 rows), j-group = (cta&15)*32.
// Warps: nt = warp&3 (8 j cols), kh = warp>>2 (K quarter of 256).
// mode 0: fp32 -> out32 ; mode 1: relu -> fp16 out16.
__device__ __forceinline__ void mma_AC(
    const __half* __restrict__ xin, const __half* __restrict__ op2,
    const __half* wS, const float* __restrict__ bias, int mode,
    float* __restrict__ out32, __half* __restrict__ out16, char* Rbase)
{
    const int c = blockIdx.x, tid = threadIdx.x;
    const int warp = tid >> 5, lane = tid & 31;
    const int b0 = (c >> 4) * 16, ng = c & 15;
    const int nt = warp & 3, kh = warp >> 2;
    __half* s_tile = (__half*)Rbase;                 // 16 x 1032 halves = 33024 B
    float*  s_part = (float*)(Rbase + 33024);        // 12 x 128 floats  = 6144 B

    // cooperative tile load: rows b0..b0+15, cols [0,512)=xin, [512,1024)=op2
    #pragma unroll
    for (int i = 0; i < 4; ++i) {
        int u = tid + i * NTHR;
        int row = u >> 7, c16 = u & 127;
        const __half* src = (c16 < 64)
            ? (xin + (size_t)(b0 + row) * DN + c16 * 8)
            : (op2 + (size_t)(b0 + row) * DN + (c16 - 64) * 8);
        *(uint4*)(s_tile + row * DN2P + c16 * 8) = *(const uint4*)src;
    }
    __syncthreads();

    float cc[4] = {0.f, 0.f, 0.f, 0.f};
    const int k0 = kh * 256;
    #pragma unroll 4
    for (int k = 0; k < 256; k += 16) {
        uint32_t A[4], Bf[2];
        ldAs(s_tile, DN2P, k0 + k, A);
        ldBs(wS, DN2P, nt * 8, k0 + k, Bf);
        mma16816(cc, A[0], A[1], A[2], A[3], Bf[0], Bf[1]);
    }
    if (kh) {
        float* p = s_part + ((kh - 1) * 4 + nt) * 128 + lane * 4;
        p[0] = cc[0]; p[1] = cc[1]; p[2] = cc[2]; p[3] = cc[3];
    }
    __syncthreads();
    if (!kh) {
        #pragma unroll
        for (int q = 0; q < 3; ++q) {
            const float* p = s_part + (q * 4 + nt) * 128 + lane * 4;
            cc[0] += p[0]; cc[1] += p[1]; cc[2] += p[2]; cc[3] += p[3];
        }
        const int g = lane >> 2, tig = lane & 3;
        const int j = ng * 32 + nt * 8 + tig * 2;
        const float bz0 = bias[j], bz1 = bias[j + 1];
        if (mode == 1) {
            float v0 = fmaxf(cc[0] + bz0, 0.f), v1 = fmaxf(cc[1] + bz1, 0.f);
            float v2 = fmaxf(cc[2] + bz0, 0.f), v3 = fmaxf(cc[3] + bz1, 0.f);
            *(__half2*)(out16 + (size_t)(b0 + g) * DN + j)     = __floats2half2_rn(v0, v1);
            *(__half2*)(out16 + (size_t)(b0 + g + 8) * DN + j) = __floats2half2_rn(v2, v3);
        } else {
            *(float2*)(out32 + (size_t)(b0 + g) * DN + j)     = make_float2(cc[0] + bz0, cc[1] + bz1);
            *(float2*)(out32 + (size_t)(b0 + g + 8) * DN + j) = make_float2(cc[2] + bz0, cc[3] + bz1);
        }
    }
}

// ---------------- stage B: softmax + einsum, CTA = batch b ----------------
__device__ __forceinline__ void stageB(char* Rbase, float* s_vec, float* s_scr) {
    const int b = blockIdx.x, tid = threadIdx.x;
    float* s_red = (float*)Rbase;                    // 8 x 512 floats = 16 KB
    float l = d_logits[(size_t)b * DN + tid];
    float vmax = warpMax(l);
    if ((tid & 31) == 0) s_scr[tid >> 5] = vmax;
    __syncthreads();
    float M = s_scr[0];
    #pragma unroll
    for (int i = 1; i < 16; ++i) M = fmaxf(M, s_scr[i]);
    float e = __expf(l - M);
    float ws = warpSum(e);
    __syncthreads();
    if ((tid & 31) == 0) s_scr[tid >> 5] = ws;
    __syncthreads();
    float S = 0.f;
    #pragma unroll
    for (int i = 0; i < 16; ++i) S += s_scr[i];
    s_vec[tid] = e * (1.0f / S);
    __syncthreads();

    // applied[b][t'] = sum_m w[m] * x16[b][m][t']
    const int mo = tid >> 6;     // m-octant (64 m each)
    const int tg = tid & 63;     // 8 t' cols
    float acc[8] = {0, 0, 0, 0, 0, 0, 0, 0};
    const __half* xb = d_x16 + (size_t)b * DN * TN;
    for (int mi = 0; mi < 64; ++mi) {
        int m_ = mo * 64 + mi;
        float w = s_vec[m_];
        uint4 v = *(const uint4*)(xb + (size_t)m_ * TN + tg * 8);
        const __half2* h2 = (const __half2*)&v;
        float2 f0 = __half22float2(h2[0]);
        float2 f1 = __half22float2(h2[1]);
        float2 f2 = __half22float2(h2[2]);
        float2 f3 = __half22float2(h2[3]);
        acc[0] = fmaf(w, f0.x, acc[0]); acc[1] = fmaf(w, f0.y, acc[1]);
        acc[2] = fmaf(w, f1.x, acc[2]); acc[3] = fmaf(w, f1.y, acc[3]);
        acc[4] = fmaf(w, f2.x, acc[4]); acc[5] = fmaf(w, f2.y, acc[5]);
        acc[6] = fmaf(w, f3.x, acc[6]); acc[7] = fmaf(w, f3.y, acc[7]);
    }
    #pragma unroll
    for (int q = 0; q < 8; ++q) s_red[mo * DN + tg * 8 + q] = acc[q];
    __syncthreads();
    float v = 0.f;
    #pragma unroll
    for (int o = 0; o < 8; ++o) v += s_red[o * DN + tid];
    d_ap16[(size_t)b * DN + tid] = __float2half(v);
}

// ---------------- stage D: gi/gh mma + GRU; weights in smem ----------------
// CTA: jt = c>>1 (j0 = jt*8), b-half = c&1. Warps: mtl = warp>>2 (b-tile),
// kh = warp&3 (K quarter of 128).
__device__ __forceinline__ void stageD(
    const __half* __restrict__ g16, const __half* __restrict__ h16o,
    const float* __restrict__ h32o, float* __restrict__ h32n, __half* __restrict__ h16n,
    const __half* wIH_s, const float* __restrict__ b_ih, const float* __restrict__ b_hh,
    char* Rbase)
{
    const int c = blockIdx.x, tid = threadIdx.x;
    const int warp = tid >> 5, lane = tid & 31;
    const int j0 = (c >> 1) * 8;
    const int mtl = warp >> 2, kh = warp & 3;
    const int b0 = ((c & 1) * 4 + mtl) * 16;
    const int k0 = kh * 128;
    float cI[3][4] = {};
    float cH[3][4] = {};
    #pragma unroll 2
    for (int k = 0; k < 128; k += 16) {
        uint32_t Ag[4], Ah[4], Bf[2];
        ldA(g16,  b0, k0 + k, Ag);
        ldA(h16o, b0, k0 + k, Ah);
        #pragma unroll
        for (int gate = 0; gate < 3; ++gate) {
            ldBs(wIH_s, DKP, gate * 8, k0 + k, Bf);            // w_ih rows
            mma16816(cI[gate], Ag[0], Ag[1], Ag[2], Ag[3], Bf[0], Bf[1]);
            ldBs(wIH_s, DKP, (3 + gate) * 8, k0 + k, Bf);      // w_hh rows
            mma16816(cH[gate], Ah[0], Ah[1], Ah[2], Ah[3], Bf[0], Bf[1]);
        }
    }
    float* s_part = (float*)Rbase;                  // 12 x 768 floats = 36864 B
    if (kh) {
        float* p = s_part + ((kh - 1) * 4 + mtl) * 768 + lane * 24;
        #pragma unroll
        for (int gg = 0; gg < 3; ++gg)
            #pragma unroll
            for (int i = 0; i < 4; ++i) { p[gg * 4 + i] = cI[gg][i]; p[12 + gg * 4 + i] = cH[gg][i]; }
    }
    __syncthreads();
    if (!kh) {
        #pragma unroll
        for (int q = 0; q < 3; ++q) {
            const float* p = s_part + (q * 4 + mtl) * 768 + lane * 24;
            #pragma unroll
            for (int gg = 0; gg < 3; ++gg)
                #pragma unroll
                for (int i = 0; i < 4; ++i) { cI[gg][i] += p[gg * 4 + i]; cH[gg][i] += p[12 + gg * 4 + i]; }
        }
        const int g = lane >> 2, tig = lane & 3;
        #pragma unroll
        for (int hi = 0; hi < 2; ++hi) {
            const int b = b0 + g + hi * 8;
            float hv[2];
            #pragma unroll
            for (int ccx = 0; ccx < 2; ++ccx) {
                const int j = j0 + tig * 2 + ccx;
                const int ri = hi * 2 + ccx;
                float ir  = cI[0][ri] + b_ih[j];
                float iz  = cI[1][ri] + b_ih[DN + j];
                float in_ = cI[2][ri] + b_ih[2 * DN + j];
                float hr  = cH[0][ri] + b_hh[j];
                float hz  = cH[1][ri] + b_hh[DN + j];
                float hn  = cH[2][ri] + b_hh[2 * DN + j];
                float r = 1.0f / (1.0f + __expf(-(ir + hr)));
                float z = 1.0f / (1.0f + __expf(-(iz + hz)));
                float n = tanhf(in_ + r * hn);
                float hold = h32o[(size_t)b * DN + j];
                float hnew = (1.0f - z) * n + z * hold;
                h32n[(size_t)b * DN + j] = hnew;
                hv[ccx] = hnew;
            }
            *(__half2*)(h16n + (size_t)b * DN + j0 + tig * 2) = __floats2half2_rn(hv[0], hv[1]);
        }
    }
}

// ---------------- final out GEMM: out[b][j] = h @ out_W.T + out_b ----------------
__device__ __forceinline__ void gemm_out(
    const __half* __restrict__ h16, const float* __restrict__ out_b,
    float* __restrict__ out, char* Rbase)
{
    const int c = blockIdx.x, tid = threadIdx.x;
    const int warp = tid >> 5, lane = tid & 31;
    const int b0 = (c >> 4) * 16, ng = c & 15;
    const int nt = warp & 3, kh = warp >> 2;
    __half* s_tile = (__half*)Rbase;                 // 16 x 520 halves = 16640 B
    float*  s_part = (float*)(Rbase + 16640);
    #pragma unroll
    for (int i = 0; i < 2; ++i) {
        int u = tid + i * NTHR;
        int row = u >> 6, c16 = u & 63;
        *(uint4*)(s_tile + row * DKP + c16 * 8)
            = *(const uint4*)(h16 + (size_t)(b0 + row) * DN + c16 * 8);
    }
    __syncthreads();
    float cc[4] = {0.f, 0.f, 0.f, 0.f};
    const int k0 = kh * 128;
    #pragma unroll 2
    for (int k = 0; k < 128; k += 16) {
        uint32_t A[4], Bf[2];
        ldAs(s_tile, DKP, k0 + k, A);
        ldB(d_wO, DN, ng * 32 + nt * 8, k0 + k, Bf);
        mma16816(cc, A[0], A[1], A[2], A[3], Bf[0], Bf[1]);
    }
    if (kh) {
        float* p = s_part + ((kh - 1) * 4 + nt) * 128 + lane * 4;
        p[0] = cc[0]; p[1] = cc[1]; p[2] = cc[2]; p[3] = cc[3];
    }
    __syncthreads();
    if (!kh) {
        #pragma unroll
        for (int q = 0; q < 3; ++q) {
            const float* p = s_part + (q * 4 + nt) * 128 + lane * 4;
            cc[0] += p[0]; cc[1] += p[1]; cc[2] += p[2]; cc[3] += p[3];
        }
        const int g = lane >> 2, tig = lane & 3;
        const int j = ng * 32 + nt * 8 + tig * 2;
        const float bz0 = out_b[j], bz1 = out_b[j + 1];
        *(float2*)(out + (size_t)(b0 + g) * DN + j)     = make_float2(cc[0] + bz0, cc[1] + bz1);
        *(float2*)(out + (size_t)(b0 + g + 8) * DN + j) = make_float2(cc[2] + bz0, cc[3] + bz1);
    }
}

// ---------------- persistent kernel ----------------
__global__ void __launch_bounds__(NTHR, 1) rnn_mma(
    const float* __restrict__ attn_b, const float* __restrict__ comb_b,
    const float* __restrict__ b_ih, const float* __restrict__ b_hh,
    const float* __restrict__ out_b, float* __restrict__ out)
{
    extern __shared__ char smem[];
    __half* wA_s  = (__half*)(smem + OFF_WA);
    __half* wC_s  = (__half*)(smem + OFF_WC);
    __half* wIH_s = (__half*)(smem + OFF_WIH);
    char*   Rbase = smem + OFF_R;
    float*  s_vec = (float*)(smem + OFF_VEC);
    float*  s_scr = (float*)(smem + OFF_SCR);

    const int c = blockIdx.x, tid = threadIdx.x;

    // ---- one-time weight preload into smem ----
    {
        const int j0AC = (c & 15) * 32;
        #pragma unroll
        for (int i = 0; i < 8; ++i) {
            int u = tid + i * NTHR;
            int row = u >> 7, c16 = u & 127;
            *(uint4*)(wA_s + row * DN2P + c16 * 8)
                = *(const uint4*)(d_wA + (size_t)(j0AC + row) * (2 * DN) + c16 * 8);
            *(uint4*)(wC_s + row * DN2P + c16 * 8)
                = *(const uint4*)(d_wC + (size_t)(j0AC + row) * (2 * DN) + c16 * 8);
        }
        const int j0D = (c >> 1) * 8;
        #pragma unroll
        for (int i = 0; i < 6; ++i) {
            int u = tid + i * NTHR;
            int row = u >> 6, c16 = u & 63;
            int mat = row / 24, rem = row % 24;
            int gate = rem >> 3, jr = rem & 7;
            const __half* src = (mat ? d_wH : d_wI)
                + (size_t)(gate * DN + j0D + jr) * DN + c16 * 8;
            *(uint4*)(wIH_s + row * DKP + c16 * 8) = *(const uint4*)src;
        }
    }
    __syncthreads();

    unsigned epoch = 0;
    for (int t = 0; t < TN; ++t) {
        const __half* xin  = d_xbm + (size_t)t * HSZ;
        const __half* h16o = d_h16[t & 1];
        // A: logits = [inp | h] @ attn_W.T + attn_b
        mma_AC(xin, h16o, wA_s, attn_b, 0, d_logits, nullptr, Rbase);
        gridbar(epoch);
        // B: softmax + einsum -> ap16
        stageB(Rbase, s_vec, s_scr);
        gridbar(epoch);
        // C: g = relu([inp | applied] @ comb_W.T + comb_b)
        mma_AC(xin, d_ap16, wC_s, comb_b, 1, nullptr, d_g16, Rbase);
        gridbar(epoch);
        // D: GRU update
        stageD(d_g16, h16o, d_h32[t & 1], d_h32[(t + 1) & 1], d_h16[(t + 1) & 1],
               wIH_s, b_ih, b_hh, Rbase);
        gridbar(epoch);
    }
    gemm_out(d_h16[0], out_b, out, Rbase);
}

// ---------------- launch ----------------
extern "C" void kernel_launch(void* const* d_in, const int* in_sizes, int n_in,
                              void* d_out, int out_size) {
    (void)in_sizes; (void)n_in; (void)out_size;
    const float* x      = (const float*)d_in[0];
    const float* attn_W = (const float*)d_in[1];
    const float* attn_b = (const float*)d_in[2];
    const float* comb_W = (const float*)d_in[3];
    const float* comb_b = (const float*)d_in[4];
    const float* w_ih   = (const float*)d_in[5];
    const float* w_hh   = (const float*)d_in[6];
    const float* b_ih   = (const float*)d_in[7];
    const float* b_hh   = (const float*)d_in[8];
    const float* out_W  = (const float*)d_in[9];
    const float* out_b  = (const float*)d_in[10];
    float* out = (float*)d_out;

    static bool attr_set = false;
    if (!attr_set) {
        cudaFuncSetAttribute(rnn_mma, cudaFuncAttributeMaxDynamicSharedMemorySize,
                             SMEM_TOTAL);
        attr_set = true;
    }

    k_init<<<(HSZ + 255) / 256, 256>>>();
    k_x16<<<2048, 256>>>(x);
    k_xbm<<<dim3(16, 16, 128), 256>>>(x);
    k_wconv<<<(3 * DN * DN + 255) / 256, 256>>>(attn_W, comb_W, w_ih, w_hh, out_W);
    rnn_mma<<<NCTA, NTHR, SMEM_TOTAL>>>(attn_b, comb_b, b_ih, b_hh, out_b, out);
}

// round 6
// speedup vs baseline: 4.4802x; 1.2588x over previous
#include <cuda_runtime.h>
#include <cuda_fp16.h>
#include <cstdint>

#define BN   128
#define DN   512
#define TN   512
#define NCTA 128
#define NTHR 512
#define HSZ  (BN * DN)   // 65536

// padded smem row strides (halves)
#define DN2P 1032   // 1024-wide rows
#define DKP  520    // 512-wide rows

// dynamic smem byte offsets
#define OFF_WA   0                       // 32 x 1032 halves = 66048 B
#define OFF_WC   66048                   // 66048 B
#define OFF_WIH  132096                  // 48 x 520 halves  = 49920 B
#define OFF_R    182016                  // scratch union    = 40960 B
#define OFF_VEC  222976                  // 512 floats
#define OFF_SCR  225024                  // 16 floats
#define SMEM_TOTAL 225088

// ---------------- device scratch ----------------
__device__ __align__(16) __half d_x16[(size_t)BN * DN * TN];   // [b][m][t]  einsum operand
__device__ __align__(16) __half d_xbm[(size_t)TN * BN * DN];   // [t][b][m]  GEMM A operand
__device__ __align__(16) __half d_wA[DN * 2 * DN];
__device__ __align__(16) __half d_wC[DN * 2 * DN];
__device__ __align__(16) __half d_wI[3 * DN * DN];
__device__ __align__(16) __half d_wH[3 * DN * DN];
__device__ __align__(16) __half d_wO[DN * DN];
__device__ __align__(16) float  d_logits[HSZ];                 // [b][j]
__device__ __align__(16) __half d_g16t[HSZ];                   // g, TILED frag layout
__device__ __align__(16) __half d_ap16[HSZ];                   // [b][t']
__device__ __align__(16) __half d_h16[2][HSZ];                 // h row-major [b][j]
__device__ __align__(16) __half d_h16t[2][HSZ];                // h TILED frag layout
__device__ unsigned d_bar_count;
__device__ unsigned d_bar_sense;

// Tiled layout: tile (bt, kt) = rows bt*16.., cols kt*16..; tile base (halves) =
// (bt*32 + kt) * 256; within tile, lane L holds the 4 A-frag u32s at halves L*8..L*8+7.

// ---------------- init kernels ----------------
__global__ void k_init() {
    int i = blockIdx.x * blockDim.x + threadIdx.x;
    if (i < HSZ) {
        d_h16[0][i]  = __float2half(0.0f);
        d_h16t[0][i] = __float2half(0.0f);
    }
    if (i == 0) { d_bar_count = 0u; d_bar_sense = 0u; }
}

__global__ void k_x16(const float* __restrict__ x) {
    size_t n = (size_t)BN * DN * TN;
    for (size_t i = (size_t)blockIdx.x * blockDim.x + threadIdx.x; i < n;
         i += (size_t)gridDim.x * blockDim.x)
        d_x16[i] = __float2half(x[i]);
}

// xbm[t][b][m] = (half)x[b][m][t]
__global__ void k_xbm(const float* __restrict__ x) {
    __shared__ float tile[32][33];
    int m0 = blockIdx.x * 32;
    int t0 = blockIdx.y * 32;
    int b  = blockIdx.z;
    int tx = threadIdx.x & 31;
    int ty = threadIdx.x >> 5;
    #pragma unroll
    for (int r = 0; r < 32; r += 8)
        tile[ty + r][tx] = x[(size_t)b * DN * TN + (size_t)(m0 + ty + r) * TN + (t0 + tx)];
    __syncthreads();
    #pragma unroll
    for (int r = 0; r < 32; r += 8)
        d_xbm[(size_t)(t0 + ty + r) * HSZ + (size_t)b * DN + (m0 + tx)]
            = __float2half(tile[tx][ty + r]);
}

__global__ void k_wconv(const float* __restrict__ aW, const float* __restrict__ cW,
                        const float* __restrict__ wi, const float* __restrict__ wh,
                        const float* __restrict__ oW) {
    int i = blockIdx.x * blockDim.x + threadIdx.x;
    if (i < DN * 2 * DN) { d_wA[i] = __float2half(aW[i]); d_wC[i] = __float2half(cW[i]); }
    if (i < 3 * DN * DN) { d_wI[i] = __float2half(wi[i]); d_wH[i] = __float2half(wh[i]); }
    if (i < DN * DN)     { d_wO[i] = __float2half(oW[i]); }
}

// ---------------- grid barrier ----------------
__device__ __forceinline__ void gridbar(unsigned& epoch) {
    __syncthreads();
    if (threadIdx.x == 0) {
        epoch += NCTA;
        __threadfence();
        unsigned a = atomicAdd(&d_bar_count, 1u) + 1u;
        if (a == epoch) {
            atomicExch(&d_bar_sense, epoch);
        } else {
            while (*(volatile unsigned*)&d_bar_sense < epoch) { }
        }
        __threadfence();
    }
    __syncthreads();
}

// ---------------- warp reductions ----------------
__device__ __forceinline__ float warpMax(float v) {
    #pragma unroll
    for (int o = 16; o; o >>= 1) v = fmaxf(v, __shfl_xor_sync(0xffffffffu, v, o));
    return v;
}
__device__ __forceinline__ float warpSum(float v) {
    #pragma unroll
    for (int o = 16; o; o >>= 1) v += __shfl_xor_sync(0xffffffffu, v, o);
    return v;
}

// ---------------- mma helpers ----------------
__device__ __forceinline__ void mma16816(float c[4], uint32_t a0, uint32_t a1,
                                         uint32_t a2, uint32_t a3,
                                         uint32_t b0, uint32_t b1) {
    asm volatile(
        "mma.sync.aligned.m16n8k16.row.col.f32.f16.f16.f32 "
        "{%0,%1,%2,%3}, {%4,%5,%6,%7}, {%8,%9}, {%0,%1,%2,%3};"
        : "+f"(c[0]), "+f"(c[1]), "+f"(c[2]), "+f"(c[3])
        : "r"(a0), "r"(a1), "r"(a2), "r"(a3), "r"(b0), "r"(b1));
}

// A fragment from TILED global array: one LDG.128
__device__ __forceinline__ void ldAt(const __half* __restrict__ base, int bt, int kt,
                                     uint32_t A[4]) {
    const int lane = threadIdx.x & 31;
    uint4 v = *(const uint4*)(base + ((size_t)(bt * 32 + kt) << 8) + lane * 8);
    A[0] = v.x; A[1] = v.y; A[2] = v.z; A[3] = v.w;
}

// B fragment from GLOBAL W [j][k]
__device__ __forceinline__ void ldB(const __half* __restrict__ W, int stride, int j0, int k,
                                    uint32_t Bf[2]) {
    const int lane = threadIdx.x & 31;
    const int g = lane >> 2, tig = lane & 3;
    const __half* p = W + (size_t)(j0 + g) * stride + k + tig * 2;
    Bf[0] = *(const uint32_t*)p;
    Bf[1] = *(const uint32_t*)(p + 8);
}

// A fragment from SMEM tile, padded row stride
__device__ __forceinline__ void ldAs(const __half* s, int stridep, int k, uint32_t A[4]) {
    const int lane = threadIdx.x & 31;
    const int g = lane >> 2, tig = lane & 3;
    const __half* p0 = s + g * stridep + k + tig * 2;
    const __half* p1 = p0 + 8 * stridep;
    A[0] = *(const uint32_t*)p0;
    A[1] = *(const uint32_t*)p1;
    A[2] = *(const uint32_t*)(p0 + 8);
    A[3] = *(const uint32_t*)(p1 + 8);
}

// B fragment from SMEM weights, padded row stride
__device__ __forceinline__ void ldBs(const __half* s, int stridep, int row0, int k,
                                     uint32_t Bf[2]) {
    const int lane = threadIdx.x & 31;
    const int g = lane >> 2, tig = lane & 3;
    const __half* p = s + (row0 + g) * stridep + k + tig * 2;
    Bf[0] = *(const uint32_t*)p;
    Bf[1] = *(const uint32_t*)(p + 8);
}

// ---------------- stages A / C ----------------
// CTA: b-tile = (c>>4)*16, j-group = (c&15)*32. Warps: nt = warp&3, kh = warp>>2.
// mode 0: fp32 -> out32 (logits). mode 1: relu -> TILED fp16 out (g16t).
__device__ __forceinline__ void mma_AC(
    const __half* __restrict__ xin, const __half* __restrict__ op2,
    const __half* wS, const float* __restrict__ bias, int mode,
    float* __restrict__ out32, __half* __restrict__ out16t, char* Rbase)
{
    const int c = blockIdx.x, tid = threadIdx.x;
    const int warp = tid >> 5, lane = tid & 31;
    const int b0 = (c >> 4) * 16, ng = c & 15;
    const int nt = warp & 3, kh = warp >> 2;
    __half* s_tile = (__half*)Rbase;                 // 16 x 1032 halves = 33024 B
    float*  s_part = (float*)(Rbase + 33024);        // 12 x 128 floats

    #pragma unroll
    for (int i = 0; i < 4; ++i) {
        int u = tid + i * NTHR;
        int row = u >> 7, c16 = u & 127;
        const __half* src = (c16 < 64)
            ? (xin + (size_t)(b0 + row) * DN + c16 * 8)
            : (op2 + (size_t)(b0 + row) * DN + (c16 - 64) * 8);
        *(uint4*)(s_tile + row * DN2P + c16 * 8) = *(const uint4*)src;
    }
    __syncthreads();

    float cc[4] = {0.f, 0.f, 0.f, 0.f};
    const int k0 = kh * 256;
    #pragma unroll 4
    for (int k = 0; k < 256; k += 16) {
        uint32_t A[4], Bf[2];
        ldAs(s_tile, DN2P, k0 + k, A);
        ldBs(wS, DN2P, nt * 8, k0 + k, Bf);
        mma16816(cc, A[0], A[1], A[2], A[3], Bf[0], Bf[1]);
    }
    if (kh) {
        float* p = s_part + ((kh - 1) * 4 + nt) * 128 + lane * 4;
        p[0] = cc[0]; p[1] = cc[1]; p[2] = cc[2]; p[3] = cc[3];
    }
    __syncthreads();
    if (!kh) {
        #pragma unroll
        for (int q = 0; q < 3; ++q) {
            const float* p = s_part + (q * 4 + nt) * 128 + lane * 4;
            cc[0] += p[0]; cc[1] += p[1]; cc[2] += p[2]; cc[3] += p[3];
        }
        const int g = lane >> 2, tig = lane & 3;
        const int j = ng * 32 + nt * 8 + tig * 2;
        const float bz0 = bias[j], bz1 = bias[j + 1];
        if (mode == 1) {
            float v0 = fmaxf(cc[0] + bz0, 0.f), v1 = fmaxf(cc[1] + bz1, 0.f);
            float v2 = fmaxf(cc[2] + bz0, 0.f), v3 = fmaxf(cc[3] + bz1, 0.f);
            // tiled write: bt = c>>4, kt = ng*2 + (nt>>1), slot-half = nt&1
            const int kt = ng * 2 + (nt >> 1);
            __half2 h0 = __floats2half2_rn(v0, v1);
            __half2 h1 = __floats2half2_rn(v2, v3);
            uint2 u;
            u.x = *(uint32_t*)&h0;
            u.y = *(uint32_t*)&h1;
            *(uint2*)(out16t + ((size_t)((c >> 4) * 32 + kt) << 8) + lane * 8 + (nt & 1) * 4) = u;
        } else {
            *(float2*)(out32 + (size_t)(b0 + g) * DN + j)     = make_float2(cc[0] + bz0, cc[1] + bz1);
            *(float2*)(out32 + (size_t)(b0 + g + 8) * DN + j) = make_float2(cc[2] + bz0, cc[3] + bz1);
        }
    }
}

// ---------------- stage B: softmax + einsum, CTA = batch b ----------------
__device__ __forceinline__ void stageB(char* Rbase, float* s_vec, float* s_scr) {
    const int b = blockIdx.x, tid = threadIdx.x;
    float* s_red = (float*)Rbase;                    // 8 x 512 floats
    float l = d_logits[(size_t)b * DN + tid];
    float vmax = warpMax(l);
    if ((tid & 31) == 0) s_scr[tid >> 5] = vmax;
    __syncthreads();
    float M = s_scr[0];
    #pragma unroll
    for (int i = 1; i < 16; ++i) M = fmaxf(M, s_scr[i]);
    float e = __expf(l - M);
    float ws = warpSum(e);
    __syncthreads();
    if ((tid & 31) == 0) s_scr[tid >> 5] = ws;
    __syncthreads();
    float S = 0.f;
    #pragma unroll
    for (int i = 0; i < 16; ++i) S += s_scr[i];
    s_vec[tid] = e * (1.0f / S);
    __syncthreads();

    const int mo = tid >> 6;
    const int tg = tid & 63;
    float acc[8] = {0, 0, 0, 0, 0, 0, 0, 0};
    const __half* xb = d_x16 + (size_t)b * DN * TN;
    for (int mi = 0; mi < 64; ++mi) {
        int m_ = mo * 64 + mi;
        float w = s_vec[m_];
        uint4 v = *(const uint4*)(xb + (size_t)m_ * TN + tg * 8);
        const __half2* h2 = (const __half2*)&v;
        float2 f0 = __half22float2(h2[0]);
        float2 f1 = __half22float2(h2[1]);
        float2 f2 = __half22float2(h2[2]);
        float2 f3 = __half22float2(h2[3]);
        acc[0] = fmaf(w, f0.x, acc[0]); acc[1] = fmaf(w, f0.y, acc[1]);
        acc[2] = fmaf(w, f1.x, acc[2]); acc[3] = fmaf(w, f1.y, acc[3]);
        acc[4] = fmaf(w, f2.x, acc[4]); acc[5] = fmaf(w, f2.y, acc[5]);
        acc[6] = fmaf(w, f3.x, acc[6]); acc[7] = fmaf(w, f3.y, acc[7]);
    }
    #pragma unroll
    for (int q = 0; q < 8; ++q) s_red[mo * DN + tg * 8 + q] = acc[q];
    __syncthreads();
    float v = 0.f;
    #pragma unroll
    for (int o = 0; o < 8; ++o) v += s_red[o * DN + tid];
    d_ap16[(size_t)b * DN + tid] = __float2half(v);
}

// ---------------- stage D: gi/gh mma + GRU ----------------
// CTA: jt = c>>1 (j0 = jt*8), b-half = c&1. Warps: mtl = warp>>2, kh = warp&3.
// A-operands (g, h_old) come from TILED arrays via single LDG.128 per fragment.
// fp32 h state lives in hreg[4] of the kh==0 epilogue lanes (persistent CTA).
__device__ __forceinline__ void stageD(
    const __half* __restrict__ g16t, const __half* __restrict__ h16to,
    __half* __restrict__ h16n, __half* __restrict__ h16tn,
    const __half* wIH_s, const float* __restrict__ b_ih, const float* __restrict__ b_hh,
    float hreg[4], char* Rbase)
{
    const int c = blockIdx.x, tid = threadIdx.x;
    const int warp = tid >> 5, lane = tid & 31;
    const int jt = c >> 1;
    const int j0 = jt * 8;
    const int mtl = warp >> 2, kh = warp & 3;
    const int bt = (c & 1) * 4 + mtl;
    const int b0 = bt * 16;
    const int kt0 = kh * 8;          // k-tile base (k0 = kh*128)
    float cI[3][4] = {};
    float cH[3][4] = {};
    #pragma unroll 2
    for (int kt = 0; kt < 8; ++kt) {
        uint32_t Ag[4], Ah[4], Bf[2];
        ldAt(g16t,  bt, kt0 + kt, Ag);
        ldAt(h16to, bt, kt0 + kt, Ah);
        const int k = (kt0 + kt) * 16;
        #pragma unroll
        for (int gate = 0; gate < 3; ++gate) {
            ldBs(wIH_s, DKP, gate * 8, k, Bf);
            mma16816(cI[gate], Ag[0], Ag[1], Ag[2], Ag[3], Bf[0], Bf[1]);
            ldBs(wIH_s, DKP, (3 + gate) * 8, k, Bf);
            mma16816(cH[gate], Ah[0], Ah[1], Ah[2], Ah[3], Bf[0], Bf[1]);
        }
    }
    float* s_part = (float*)Rbase;                  // 12 x 768 floats
    if (kh) {
        float* p = s_part + ((kh - 1) * 4 + mtl) * 768 + lane * 24;
        #pragma unroll
        for (int gg = 0; gg < 3; ++gg)
            #pragma unroll
            for (int i = 0; i < 4; ++i) { p[gg * 4 + i] = cI[gg][i]; p[12 + gg * 4 + i] = cH[gg][i]; }
    }
    __syncthreads();
    if (!kh) {
        #pragma unroll
        for (int q = 0; q < 3; ++q) {
            const float* p = s_part + (q * 4 + mtl) * 768 + lane * 24;
            #pragma unroll
            for (int gg = 0; gg < 3; ++gg)
                #pragma unroll
                for (int i = 0; i < 4; ++i) { cI[gg][i] += p[gg * 4 + i]; cH[gg][i] += p[12 + gg * 4 + i]; }
        }
        const int g = lane >> 2, tig = lane & 3;
        float hv[2][2];
        #pragma unroll
        for (int hi = 0; hi < 2; ++hi) {
            const int b = b0 + g + hi * 8;
            #pragma unroll
            for (int ccx = 0; ccx < 2; ++ccx) {
                const int j = j0 + tig * 2 + ccx;
                const int ri = hi * 2 + ccx;
                float ir  = cI[0][ri] + b_ih[j];
                float iz  = cI[1][ri] + b_ih[DN + j];
                float in_ = cI[2][ri] + b_ih[2 * DN + j];
                float hr  = cH[0][ri] + b_hh[j];
                float hz  = cH[1][ri] + b_hh[DN + j];
                float hn  = cH[2][ri] + b_hh[2 * DN + j];
                float r = 1.0f / (1.0f + __expf(-(ir + hr)));
                float z = 1.0f / (1.0f + __expf(-(iz + hz)));
                float n = tanhf(in_ + r * hn);
                float hold = hreg[ri];
                float hnew = (1.0f - z) * n + z * hold;
                hreg[ri] = hnew;
                hv[hi][ccx] = hnew;
            }
            // row-major write (for stage A tile loads)
            *(__half2*)(h16n + (size_t)b * DN + j0 + tig * 2)
                = __floats2half2_rn(hv[hi][0], hv[hi][1]);
        }
        // tiled write (for next step's stage D)
        {
            const int kt = jt >> 1;
            __half2 h0 = __floats2half2_rn(hv[0][0], hv[0][1]);
            __half2 h1 = __floats2half2_rn(hv[1][0], hv[1][1]);
            uint2 u;
            u.x = *(uint32_t*)&h0;
            u.y = *(uint32_t*)&h1;
            *(uint2*)(h16tn + ((size_t)(bt * 32 + kt) << 8) + lane * 8 + (jt & 1) * 4) = u;
        }
    }
}

// ---------------- final out GEMM ----------------
__device__ __forceinline__ void gemm_out(
    const __half* __restrict__ h16, const float* __restrict__ out_b,
    float* __restrict__ out, char* Rbase)
{
    const int c = blockIdx.x, tid = threadIdx.x;
    const int warp = tid >> 5, lane = tid & 31;
    const int b0 = (c >> 4) * 16, ng = c & 15;
    const int nt = warp & 3, kh = warp >> 2;
    __half* s_tile = (__half*)Rbase;
    float*  s_part = (float*)(Rbase + 16640);
    #pragma unroll
    for (int i = 0; i < 2; ++i) {
        int u = tid + i * NTHR;
        int row = u >> 6, c16 = u & 63;
        *(uint4*)(s_tile + row * DKP + c16 * 8)
            = *(const uint4*)(h16 + (size_t)(b0 + row) * DN + c16 * 8);
    }
    __syncthreads();
    float cc[4] = {0.f, 0.f, 0.f, 0.f};
    const int k0 = kh * 128;
    #pragma unroll 2
    for (int k = 0; k < 128; k += 16) {
        uint32_t A[4], Bf[2];
        ldAs(s_tile, DKP, k0 + k, A);
        ldB(d_wO, DN, ng * 32 + nt * 8, k0 + k, Bf);
        mma16816(cc, A[0], A[1], A[2], A[3], Bf[0], Bf[1]);
    }
    if (kh) {
        float* p = s_part + ((kh - 1) * 4 + nt) * 128 + lane * 4;
        p[0] = cc[0]; p[1] = cc[1]; p[2] = cc[2]; p[3] = cc[3];
    }
    __syncthreads();
    if (!kh) {
        #pragma unroll
        for (int q = 0; q < 3; ++q) {
            const float* p = s_part + (q * 4 + nt) * 128 + lane * 4;
            cc[0] += p[0]; cc[1] += p[1]; cc[2] += p[2]; cc[3] += p[3];
        }
        const int g = lane >> 2, tig = lane & 3;
        const int j = ng * 32 + nt * 8 + tig * 2;
        const float bz0 = out_b[j], bz1 = out_b[j + 1];
        *(float2*)(out + (size_t)(b0 + g) * DN + j)     = make_float2(cc[0] + bz0, cc[1] + bz1);
        *(float2*)(out + (size_t)(b0 + g + 8) * DN + j) = make_float2(cc[2] + bz0, cc[3] + bz1);
    }
}

// ---------------- persistent kernel ----------------
__global__ void __launch_bounds__(NTHR, 1) rnn_mma(
    const float* __restrict__ attn_b, const float* __restrict__ comb_b,
    const float* __restrict__ b_ih, const float* __restrict__ b_hh,
    const float* __restrict__ out_b, float* __restrict__ out)
{
    extern __shared__ char smem[];
    __half* wA_s  = (__half*)(smem + OFF_WA);
    __half* wC_s  = (__half*)(smem + OFF_WC);
    __half* wIH_s = (__half*)(smem + OFF_WIH);
    char*   Rbase = smem + OFF_R;
    float*  s_vec = (float*)(smem + OFF_VEC);
    float*  s_scr = (float*)(smem + OFF_SCR);

    const int c = blockIdx.x, tid = threadIdx.x;

    // ---- one-time weight preload into smem ----
    {
        const int j0AC = (c & 15) * 32;
        #pragma unroll
        for (int i = 0; i < 8; ++i) {
            int u = tid + i * NTHR;
            int row = u >> 7, c16 = u & 127;
            *(uint4*)(wA_s + row * DN2P + c16 * 8)
                = *(const uint4*)(d_wA + (size_t)(j0AC + row) * (2 * DN) + c16 * 8);
            *(uint4*)(wC_s + row * DN2P + c16 * 8)
                = *(const uint4*)(d_wC + (size_t)(j0AC + row) * (2 * DN) + c16 * 8);
        }
        const int j0D = (c >> 1) * 8;
        #pragma unroll
        for (int i = 0; i < 6; ++i) {
            int u = tid + i * NTHR;
            int row = u >> 6, c16 = u & 63;
            int mat = row / 24, rem = row % 24;
            int gate = rem >> 3, jr = rem & 7;
            const __half* src = (mat ? d_wH : d_wI)
                + (size_t)(gate * DN + j0D + jr) * DN + c16 * 8;
            *(uint4*)(wIH_s + row * DKP + c16 * 8) = *(const uint4*)src;
        }
    }
    __syncthreads();

    float hreg[4] = {0.f, 0.f, 0.f, 0.f};   // fp32 h state, lives in epilogue lanes
    unsigned epoch = 0;
    for (int t = 0; t < TN; ++t) {
        const __half* xin = d_xbm + (size_t)t * HSZ;
        // A: logits = [inp | h] @ attn_W.T + attn_b
        mma_AC(xin, d_h16[t & 1], wA_s, attn_b, 0, d_logits, nullptr, Rbase);
        gridbar(epoch);
        // B: softmax + einsum -> ap16
        stageB(Rbase, s_vec, s_scr);
        gridbar(epoch);
        // C: g = relu([inp | applied] @ comb_W.T + comb_b) -> tiled g16t
        mma_AC(xin, d_ap16, wC_s, comb_b, 1, nullptr, d_g16t, Rbase);
        gridbar(epoch);
        // D: GRU update
        stageD(d_g16t, d_h16t[t & 1], d_h16[(t + 1) & 1], d_h16t[(t + 1) & 1],
               wIH_s, b_ih, b_hh, hreg, Rbase);
        gridbar(epoch);
    }
    gemm_out(d_h16[0], out_b, out, Rbase);
}

// ---------------- launch ----------------
extern "C" void kernel_launch(void* const* d_in, const int* in_sizes, int n_in,
                              void* d_out, int out_size) {
    (void)in_sizes; (void)n_in; (void)out_size;
    const float* x      = (const float*)d_in[0];
    const float* attn_W = (const float*)d_in[1];
    const float* attn_b = (const float*)d_in[2];
    const float* comb_W = (const float*)d_in[3];
    const float* comb_b = (const float*)d_in[4];
    const float* w_ih   = (const float*)d_in[5];
    const float* w_hh   = (const float*)d_in[6];
    const float* b_ih   = (const float*)d_in[7];
    const float* b_hh   = (const float*)d_in[8];
    const float* out_W  = (const float*)d_in[9];
    const float* out_b  = (const float*)d_in[10];
    float* out = (float*)d_out;

    static bool attr_set = false;
    if (!attr_set) {
        cudaFuncSetAttribute(rnn_mma, cudaFuncAttributeMaxDynamicSharedMemorySize,
                             SMEM_TOTAL);
        attr_set = true;
    }

    k_init<<<(HSZ + 255) / 256, 256>>>();
    k_x16<<<2048, 256>>>(x);
    k_xbm<<<dim3(16, 16, 128), 256>>>(x);
    k_wconv<<<(3 * DN * DN + 255) / 256, 256>>>(attn_W, comb_W, w_ih, w_hh, out_W);
    rnn_mma<<<NCTA, NTHR, SMEM_TOTAL>>>(attn_b, comb_b, b_ih, b_hh, out_b, out);
}

// round 7
// speedup vs baseline: 4.6064x; 1.0282x over previous
#include <cuda_runtime.h>
#include <cuda_fp16.h>
#include <cstdint>

#define BN   128
#define DN   512
#define TN   512
#define NCTA 128
#define NTHR 512
#define HSZ  (BN * DN)   // 65536

// padded smem row strides (halves)
#define DN2P 1032   // 1024-wide rows
#define DKP  520    // 512-wide rows

// dynamic smem byte offsets
#define OFF_WA   0                       // 32 x 1032 halves = 66048 B
#define OFF_WC   66048                   // 66048 B
#define OFF_WIH  132096                  // 48 x 520 halves  = 49920 B
#define OFF_R    182016                  // scratch union    = 40960 B
#define OFF_VEC  222976                  // 512 floats
#define OFF_SCR  225024                  // 16 floats
#define SMEM_TOTAL 225088

// ---------------- device scratch ----------------
__device__ __align__(16) __half d_x16[(size_t)BN * DN * TN];   // [b][m][t]  einsum operand
__device__ __align__(16) __half d_xbm[(size_t)TN * BN * DN];   // [t][b][m]  GEMM A operand
__device__ __align__(16) __half d_wA[DN * 2 * DN];
__device__ __align__(16) __half d_wC[DN * 2 * DN];
__device__ __align__(16) __half d_wI[3 * DN * DN];
__device__ __align__(16) __half d_wH[3 * DN * DN];
__device__ __align__(16) __half d_wO[DN * DN];
__device__ __align__(16) float  d_elog[HSZ];                   // exp(logit) [b][j]
__device__ __align__(16) float  d_Spart[BN * 64];              // per-(b, jgroup*4+nt) exp partial sums
__device__ __align__(16) __half d_g16t[HSZ];                   // g, TILED frag layout
__device__ __align__(16) __half d_ap16[HSZ];                   // [b][t']
__device__ __align__(16) __half d_h16[2][HSZ];                 // h row-major [b][j]
__device__ __align__(16) __half d_h16t[2][HSZ];                // h TILED frag layout
__device__ unsigned d_bar_count;
__device__ unsigned d_bar_sense;

// Tiled layout: tile (bt, kt); base (halves) = (bt*32 + kt)*256; lane L holds
// its 4 A-frag u32s at halves L*8..L*8+7.

// ---------------- merged prep kernel ----------------
// blocks [0, 32768): xbm transpose (+ a 1024-elem slice of x16 conversion)
// blocks [32768, 35840): weight conversion (3*DN*DN indices)
// blocks [35840, 36096): h init + barrier init
__global__ void k_prep(const float* __restrict__ x,
                       const float* __restrict__ aW, const float* __restrict__ cW,
                       const float* __restrict__ wi, const float* __restrict__ wh,
                       const float* __restrict__ oW) {
    const int bx = blockIdx.x, tid = threadIdx.x;
    if (bx < 32768) {
        // x16 slice: 256 float4 per block
        {
            const float4* xs = (const float4*)x;
            size_t i4 = (size_t)bx * 256 + tid;
            float4 v = xs[i4];
            __half2 h0 = __floats2half2_rn(v.x, v.y);
            __half2 h1 = __floats2half2_rn(v.z, v.w);
            *(__half2*)(d_x16 + i4 * 4)     = h0;
            *(__half2*)(d_x16 + i4 * 4 + 2) = h1;
        }
        // xbm transpose
        __shared__ float tile[32][33];
        int m0 = (bx & 15) * 32;
        int t0 = ((bx >> 4) & 15) * 32;
        int b  = bx >> 8;
        int tx = tid & 31;
        int ty = tid >> 5;
        #pragma unroll
        for (int r = 0; r < 32; r += 8)
            tile[ty + r][tx] = x[(size_t)b * DN * TN + (size_t)(m0 + ty + r) * TN + (t0 + tx)];
        __syncthreads();
        #pragma unroll
        for (int r = 0; r < 32; r += 8)
            d_xbm[(size_t)(t0 + ty + r) * HSZ + (size_t)b * DN + (m0 + tx)]
                = __float2half(tile[tx][ty + r]);
    } else if (bx < 35840) {
        int i = (bx - 32768) * 256 + tid;
        if (i < DN * 2 * DN) { d_wA[i] = __float2half(aW[i]); d_wC[i] = __float2half(cW[i]); }
        d_wI[i] = __float2half(wi[i]);
        d_wH[i] = __float2half(wh[i]);
        if (i < DN * DN) d_wO[i] = __float2half(oW[i]);
    } else {
        int i = (bx - 35840) * 256 + tid;
        if (i < HSZ) {
            d_h16[0][i]  = __float2half(0.0f);
            d_h16t[0][i] = __float2half(0.0f);
        }
        if (i == 0) { d_bar_count = 0u; d_bar_sense = 0u; }
    }
}

// ---------------- split grid barrier ----------------
__device__ __forceinline__ void bar_arrive(unsigned& epoch) {
    __syncthreads();
    if (threadIdx.x == 0) {
        epoch += NCTA;
        __threadfence();
        unsigned a = atomicAdd(&d_bar_count, 1u) + 1u;
        if (a == epoch) atomicExch(&d_bar_sense, epoch);
    }
}
__device__ __forceinline__ void bar_wait(unsigned epoch) {
    if (threadIdx.x == 0) {
        while (*(volatile unsigned*)&d_bar_sense < epoch) { }
        __threadfence();
    }
    __syncthreads();
}

// ---------------- warp reduction ----------------
__device__ __forceinline__ float warpSum(float v) {
    #pragma unroll
    for (int o = 16; o; o >>= 1) v += __shfl_xor_sync(0xffffffffu, v, o);
    return v;
}

// ---------------- mma helpers ----------------
__device__ __forceinline__ void mma16816(float c[4], uint32_t a0, uint32_t a1,
                                         uint32_t a2, uint32_t a3,
                                         uint32_t b0, uint32_t b1) {
    asm volatile(
        "mma.sync.aligned.m16n8k16.row.col.f32.f16.f16.f32 "
        "{%0,%1,%2,%3}, {%4,%5,%6,%7}, {%8,%9}, {%0,%1,%2,%3};"
        : "+f"(c[0]), "+f"(c[1]), "+f"(c[2]), "+f"(c[3])
        : "r"(a0), "r"(a1), "r"(a2), "r"(a3), "r"(b0), "r"(b1));
}

__device__ __forceinline__ void ldAt(const __half* __restrict__ base, int bt, int kt,
                                     uint32_t A[4]) {
    const int lane = threadIdx.x & 31;
    uint4 v = *(const uint4*)(base + ((size_t)(bt * 32 + kt) << 8) + lane * 8);
    A[0] = v.x; A[1] = v.y; A[2] = v.z; A[3] = v.w;
}

__device__ __forceinline__ void ldB(const __half* __restrict__ W, int stride, int j0, int k,
                                    uint32_t Bf[2]) {
    const int lane = threadIdx.x & 31;
    const int g = lane >> 2, tig = lane & 3;
    const __half* p = W + (size_t)(j0 + g) * stride + k + tig * 2;
    Bf[0] = *(const uint32_t*)p;
    Bf[1] = *(const uint32_t*)(p + 8);
}

__device__ __forceinline__ void ldAs(const __half* s, int stridep, int k, uint32_t A[4]) {
    const int lane = threadIdx.x & 31;
    const int g = lane >> 2, tig = lane & 3;
    const __half* p0 = s + g * stridep + k + tig * 2;
    const __half* p1 = p0 + 8 * stridep;
    A[0] = *(const uint32_t*)p0;
    A[1] = *(const uint32_t*)p1;
    A[2] = *(const uint32_t*)(p0 + 8);
    A[3] = *(const uint32_t*)(p1 + 8);
}

__device__ __forceinline__ void ldBs(const __half* s, int stridep, int row0, int k,
                                     uint32_t Bf[2]) {
    const int lane = threadIdx.x & 31;
    const int g = lane >> 2, tig = lane & 3;
    const __half* p = s + (row0 + g) * stridep + k + tig * 2;
    Bf[0] = *(const uint32_t*)p;
    Bf[1] = *(const uint32_t*)(p + 8);
}

// ---------------- half-tile loader for stages A/C ----------------
// halfsel 0: cols 0..511 (xin side); halfsel 1: cols 512..1023 (op2 side)
__device__ __forceinline__ void load_half(const __half* __restrict__ src, __half* s_tile,
                                          int b0, int halfsel) {
    const int tid = threadIdx.x;
    #pragma unroll
    for (int i = 0; i < 2; ++i) {
        int u = tid + i * NTHR;
        int row = u >> 6, cc = u & 63;
        *(uint4*)(s_tile + row * DN2P + (halfsel * 64 + cc) * 8)
            = *(const uint4*)(src + (size_t)(b0 + row) * DN + cc * 8);
    }
}

// ---------------- stages A / C compute (tile already in smem) ----------------
// mode 0: exp epilogue -> d_elog + d_Spart. mode 1: relu -> TILED fp16 g16t.
__device__ __forceinline__ void mma_AC(
    const __half* wS, const float* __restrict__ bias, int mode,
    __half* __restrict__ out16t, char* Rbase)
{
    const int c = blockIdx.x, tid = threadIdx.x;
    const int warp = tid >> 5, lane = tid & 31;
    const int b0 = (c >> 4) * 16, ng = c & 15;
    const int nt = warp & 3, kh = warp >> 2;
    __half* s_tile = (__half*)Rbase;
    float*  s_part = (float*)(Rbase + 33024);

    float cc[4] = {0.f, 0.f, 0.f, 0.f};
    const int k0 = kh * 256;
    #pragma unroll 4
    for (int k = 0; k < 256; k += 16) {
        uint32_t A[4], Bf[2];
        ldAs(s_tile, DN2P, k0 + k, A);
        ldBs(wS, DN2P, nt * 8, k0 + k, Bf);
        mma16816(cc, A[0], A[1], A[2], A[3], Bf[0], Bf[1]);
    }
    if (kh) {
        float* p = s_part + ((kh - 1) * 4 + nt) * 128 + lane * 4;
        p[0] = cc[0]; p[1] = cc[1]; p[2] = cc[2]; p[3] = cc[3];
    }
    __syncthreads();
    if (!kh) {
        #pragma unroll
        for (int q = 0; q < 3; ++q) {
            const float* p = s_part + (q * 4 + nt) * 128 + lane * 4;
            cc[0] += p[0]; cc[1] += p[1]; cc[2] += p[2]; cc[3] += p[3];
        }
        const int g = lane >> 2, tig = lane & 3;
        const int j = ng * 32 + nt * 8 + tig * 2;
        const float bz0 = bias[j], bz1 = bias[j + 1];
        if (mode == 1) {
            float v0 = fmaxf(cc[0] + bz0, 0.f), v1 = fmaxf(cc[1] + bz1, 0.f);
            float v2 = fmaxf(cc[2] + bz0, 0.f), v3 = fmaxf(cc[3] + bz1, 0.f);
            const int kt = ng * 2 + (nt >> 1);
            __half2 h0 = __floats2half2_rn(v0, v1);
            __half2 h1 = __floats2half2_rn(v2, v3);
            uint2 u;
            u.x = *(uint32_t*)&h0;
            u.y = *(uint32_t*)&h1;
            *(uint2*)(out16t + ((size_t)((c >> 4) * 32 + kt) << 8) + lane * 8 + (nt & 1) * 4) = u;
        } else {
            // max-free softmax numerator: e = exp(logit); also per-warp partial sums
            float e0 = __expf(cc[0] + bz0), e1 = __expf(cc[1] + bz1);
            float e2 = __expf(cc[2] + bz0), e3 = __expf(cc[3] + bz1);
            *(float2*)(d_elog + (size_t)(b0 + g) * DN + j)     = make_float2(e0, e1);
            *(float2*)(d_elog + (size_t)(b0 + g + 8) * DN + j) = make_float2(e2, e3);
            float s01 = e0 + e1, s23 = e2 + e3;
            s01 += __shfl_xor_sync(0xffffffffu, s01, 1);
            s23 += __shfl_xor_sync(0xffffffffu, s23, 1);
            s01 += __shfl_xor_sync(0xffffffffu, s01, 2);
            s23 += __shfl_xor_sync(0xffffffffu, s23, 2);
            if (tig == 0) {
                d_Spart[(b0 + g) * 64 + ng * 4 + nt]     = s01;
                d_Spart[(b0 + g + 8) * 64 + ng * 4 + nt] = s23;
            }
        }
    }
}

// ---------------- stage B: einsum (softmax already folded), CTA = batch b ----------------
__device__ __forceinline__ void fma8(float acc[8], uint4 v, float w) {
    const __half2* h2 = (const __half2*)&v;
    float2 f0 = __half22float2(h2[0]);
    float2 f1 = __half22float2(h2[1]);
    float2 f2 = __half22float2(h2[2]);
    float2 f3 = __half22float2(h2[3]);
    acc[0] = fmaf(w, f0.x, acc[0]); acc[1] = fmaf(w, f0.y, acc[1]);
    acc[2] = fmaf(w, f1.x, acc[2]); acc[3] = fmaf(w, f1.y, acc[3]);
    acc[4] = fmaf(w, f2.x, acc[4]); acc[5] = fmaf(w, f2.y, acc[5]);
    acc[6] = fmaf(w, f3.x, acc[6]); acc[7] = fmaf(w, f3.y, acc[7]);
}

__device__ __forceinline__ void stageB(char* Rbase, float* s_vec, float* s_scr) {
    const int b = blockIdx.x, tid = threadIdx.x;
    const int warp = tid >> 5, lane = tid & 31;
    float* s_red = (float*)Rbase;                    // 8 x 512 floats
    // S = sum of 64 partials (warp 0 covers slots 0..31, warp 1 covers 32..63, ...)
    float part = d_Spart[b * 64 + (tid & 63)];
    s_vec[tid] = d_elog[(size_t)b * DN + tid];       // unnormalized weights
    float ws = warpSum(part);
    if (lane == 0) s_scr[warp] = ws;
    __syncthreads();
    const float inv = 1.0f / (s_scr[0] + s_scr[1]);

    const int mo = tid >> 6;
    const int tg = tid & 63;
    float acc[8] = {0, 0, 0, 0, 0, 0, 0, 0};
    const __half* xrow = d_x16 + (size_t)b * DN * TN + (size_t)(mo * 64) * TN + tg * 8;
    const float* wv = s_vec + mo * 64;
    #pragma unroll 1
    for (int mi = 0; mi < 64; mi += 4) {
        uint4 v0 = *(const uint4*)(xrow);
        uint4 v1 = *(const uint4*)(xrow + TN);
        uint4 v2 = *(const uint4*)(xrow + 2 * TN);
        uint4 v3 = *(const uint4*)(xrow + 3 * TN);
        xrow += 4 * TN;
        float w0 = wv[mi], w1 = wv[mi + 1], w2 = wv[mi + 2], w3 = wv[mi + 3];
        fma8(acc, v0, w0);
        fma8(acc, v1, w1);
        fma8(acc, v2, w2);
        fma8(acc, v3, w3);
    }
    #pragma unroll
    for (int q = 0; q < 8; ++q) s_red[mo * DN + tg * 8 + q] = acc[q];
    __syncthreads();
    float v = 0.f;
    #pragma unroll
    for (int o = 0; o < 8; ++o) v += s_red[o * DN + tid];
    d_ap16[(size_t)b * DN + tid] = __float2half(v * inv);
}

// ---------------- stage D: gi/gh mma + GRU ----------------
__device__ __forceinline__ void stageD(
    const __half* __restrict__ g16t, const __half* __restrict__ h16to,
    __half* __restrict__ h16n, __half* __restrict__ h16tn,
    const __half* wIH_s, const float* __restrict__ b_ih, const float* __restrict__ b_hh,
    float hreg[4], char* Rbase)
{
    const int c = blockIdx.x, tid = threadIdx.x;
    const int warp = tid >> 5, lane = tid & 31;
    const int jt = c >> 1;
    const int j0 = jt * 8;
    const int mtl = warp >> 2, kh = warp & 3;
    const int bt = (c & 1) * 4 + mtl;
    const int b0 = bt * 16;
    const int kt0 = kh * 8;
    float cI[3][4] = {};
    float cH[3][4] = {};
    #pragma unroll 2
    for (int kt = 0; kt < 8; ++kt) {
        uint32_t Ag[4], Ah[4], Bf[2];
        ldAt(g16t,  bt, kt0 + kt, Ag);
        ldAt(h16to, bt, kt0 + kt, Ah);
        const int k = (kt0 + kt) * 16;
        #pragma unroll
        for (int gate = 0; gate < 3; ++gate) {
            ldBs(wIH_s, DKP, gate * 8, k, Bf);
            mma16816(cI[gate], Ag[0], Ag[1], Ag[2], Ag[3], Bf[0], Bf[1]);
            ldBs(wIH_s, DKP, (3 + gate) * 8, k, Bf);
            mma16816(cH[gate], Ah[0], Ah[1], Ah[2], Ah[3], Bf[0], Bf[1]);
        }
    }
    float* s_part = (float*)Rbase;                  // 12 x 768 floats
    if (kh) {
        float* p = s_part + ((kh - 1) * 4 + mtl) * 768 + lane * 24;
        #pragma unroll
        for (int gg = 0; gg < 3; ++gg)
            #pragma unroll
            for (int i = 0; i < 4; ++i) { p[gg * 4 + i] = cI[gg][i]; p[12 + gg * 4 + i] = cH[gg][i]; }
    }
    __syncthreads();
    if (!kh) {
        #pragma unroll
        for (int q = 0; q < 3; ++q) {
            const float* p = s_part + (q * 4 + mtl) * 768 + lane * 24;
            #pragma unroll
            for (int gg = 0; gg < 3; ++gg)
                #pragma unroll
                for (int i = 0; i < 4; ++i) { cI[gg][i] += p[gg * 4 + i]; cH[gg][i] += p[12 + gg * 4 + i]; }
        }
        const int g = lane >> 2, tig = lane & 3;
        float hv[2][2];
        #pragma unroll
        for (int hi = 0; hi < 2; ++hi) {
            const int b = b0 + g + hi * 8;
            #pragma unroll
            for (int ccx = 0; ccx < 2; ++ccx) {
                const int j = j0 + tig * 2 + ccx;
                const int ri = hi * 2 + ccx;
                float ir  = cI[0][ri] + b_ih[j];
                float iz  = cI[1][ri] + b_ih[DN + j];
                float in_ = cI[2][ri] + b_ih[2 * DN + j];
                float hr  = cH[0][ri] + b_hh[j];
                float hz  = cH[1][ri] + b_hh[DN + j];
                float hn  = cH[2][ri] + b_hh[2 * DN + j];
                float r = 1.0f / (1.0f + __expf(-(ir + hr)));
                float z = 1.0f / (1.0f + __expf(-(iz + hz)));
                float n = tanhf(in_ + r * hn);
                float hold = hreg[ri];
                float hnew = (1.0f - z) * n + z * hold;
                hreg[ri] = hnew;
                hv[hi][ccx] = hnew;
            }
            *(__half2*)(h16n + (size_t)b * DN + j0 + tig * 2)
                = __floats2half2_rn(hv[hi][0], hv[hi][1]);
        }
        {
            const int kt = jt >> 1;
            __half2 h0 = __floats2half2_rn(hv[0][0], hv[0][1]);
            __half2 h1 = __floats2half2_rn(hv[1][0], hv[1][1]);
            uint2 u;
            u.x = *(uint32_t*)&h0;
            u.y = *(uint32_t*)&h1;
            *(uint2*)(h16tn + ((size_t)(bt * 32 + kt) << 8) + lane * 8 + (jt & 1) * 4) = u;
        }
    }
}

// ---------------- final out GEMM ----------------
__device__ __forceinline__ void gemm_out(
    const __half* __restrict__ h16, const float* __restrict__ out_b,
    float* __restrict__ out, char* Rbase)
{
    const int c = blockIdx.x, tid = threadIdx.x;
    const int warp = tid >> 5, lane = tid & 31;
    const int b0 = (c >> 4) * 16, ng = c & 15;
    const int nt = warp & 3, kh = warp >> 2;
    __half* s_tile = (__half*)Rbase;
    float*  s_part = (float*)(Rbase + 16640);
    #pragma unroll
    for (int i = 0; i < 2; ++i) {
        int u = tid + i * NTHR;
        int row = u >> 6, c16 = u & 63;
        *(uint4*)(s_tile + row * DKP + c16 * 8)
            = *(const uint4*)(h16 + (size_t)(b0 + row) * DN + c16 * 8);
    }
    __syncthreads();
    float cc[4] = {0.f, 0.f, 0.f, 0.f};
    const int k0 = kh * 128;
    #pragma unroll 2
    for (int k = 0; k < 128; k += 16) {
        uint32_t A[4], Bf[2];
        ldAs(s_tile, DKP, k0 + k, A);
        ldB(d_wO, DN, ng * 32 + nt * 8, k0 + k, Bf);
        mma16816(cc, A[0], A[1], A[2], A[3], Bf[0], Bf[1]);
    }
    if (kh) {
        float* p = s_part + ((kh - 1) * 4 + nt) * 128 + lane * 4;
        p[0] = cc[0]; p[1] = cc[1]; p[2] = cc[2]; p[3] = cc[3];
    }
    __syncthreads();
    if (!kh) {
        #pragma unroll
        for (int q = 0; q < 3; ++q) {
            const float* p = s_part + (q * 4 + nt) * 128 + lane * 4;
            cc[0] += p[0]; cc[1] += p[1]; cc[2] += p[2]; cc[3] += p[3];
        }
        const int g = lane >> 2, tig = lane & 3;
        const int j = ng * 32 + nt * 8 + tig * 2;
        const float bz0 = out_b[j], bz1 = out_b[j + 1];
        *(float2*)(out + (size_t)(b0 + g) * DN + j)     = make_float2(cc[0] + bz0, cc[1] + bz1);
        *(float2*)(out + (size_t)(b0 + g + 8) * DN + j) = make_float2(cc[2] + bz0, cc[3] + bz1);
    }
}

// ---------------- persistent kernel ----------------
__global__ void __launch_bounds__(NTHR, 1) rnn_mma(
    const float* __restrict__ attn_b, const float* __restrict__ comb_b,
    const float* __restrict__ b_ih, const float* __restrict__ b_hh,
    const float* __restrict__ out_b, float* __restrict__ out)
{
    extern __shared__ char smem[];
    __half* wA_s  = (__half*)(smem + OFF_WA);
    __half* wC_s  = (__half*)(smem + OFF_WC);
    __half* wIH_s = (__half*)(smem + OFF_WIH);
    char*   Rbase = smem + OFF_R;
    __half* s_tile = (__half*)Rbase;
    float*  s_vec = (float*)(smem + OFF_VEC);
    float*  s_scr = (float*)(smem + OFF_SCR);

    const int c = blockIdx.x, tid = threadIdx.x;
    const int b0AC = (c >> 4) * 16;

    // ---- one-time weight preload into smem ----
    {
        const int j0AC = (c & 15) * 32;
        #pragma unroll
        for (int i = 0; i < 8; ++i) {
            int u = tid + i * NTHR;
            int row = u >> 7, c16 = u & 127;
            *(uint4*)(wA_s + row * DN2P + c16 * 8)
                = *(const uint4*)(d_wA + (size_t)(j0AC + row) * (2 * DN) + c16 * 8);
            *(uint4*)(wC_s + row * DN2P + c16 * 8)
                = *(const uint4*)(d_wC + (size_t)(j0AC + row) * (2 * DN) + c16 * 8);
        }
        const int j0D = (c >> 1) * 8;
        #pragma unroll
        for (int i = 0; i < 6; ++i) {
            int u = tid + i * NTHR;
            int row = u >> 6, c16 = u & 63;
            int mat = row / 24, rem = row % 24;
            int gate = rem >> 3, jr = rem & 7;
            const __half* src = (mat ? d_wH : d_wI)
                + (size_t)(gate * DN + j0D + jr) * DN + c16 * 8;
            *(uint4*)(wIH_s + row * DKP + c16 * 8) = *(const uint4*)src;
        }
    }
    __syncthreads();

    float hreg[4] = {0.f, 0.f, 0.f, 0.f};
    unsigned epoch = 0;

    // prologue: xin tile for t=0
    load_half(d_xbm, s_tile, b0AC, 0);

    for (int t = 0; t < TN; ++t) {
        // ---- stage A (xin half already loaded; h ready from D-barrier) ----
        load_half(d_h16[t & 1], s_tile, b0AC, 1);
        __syncthreads();
        mma_AC(wA_s, attn_b, 0, nullptr, Rbase);
        bar_arrive(epoch);
        bar_wait(epoch);
        // ---- stage B: einsum ----
        stageB(Rbase, s_vec, s_scr);
        bar_arrive(epoch);
        load_half(d_xbm + (size_t)t * HSZ, s_tile, b0AC, 0);   // overlap barrier wait
        bar_wait(epoch);
        // ---- stage C ----
        load_half(d_ap16, s_tile, b0AC, 1);
        __syncthreads();
        mma_AC(wC_s, comb_b, 1, d_g16t, Rbase);
        bar_arrive(epoch);
        bar_wait(epoch);
        // ---- stage D ----
        stageD(d_g16t, d_h16t[t & 1], d_h16[(t + 1) & 1], d_h16t[(t + 1) & 1],
               wIH_s, b_ih, b_hh, hreg, Rbase);
        bar_arrive(epoch);
        if (t + 1 < TN)
            load_half(d_xbm + (size_t)(t + 1) * HSZ, s_tile, b0AC, 0);  // overlap
        bar_wait(epoch);
    }
    gemm_out(d_h16[0], out_b, out, Rbase);
}

// ---------------- launch (exactly 2 kernels -> ncu -s 5 hits rnn_mma) ----------------
extern "C" void kernel_launch(void* const* d_in, const int* in_sizes, int n_in,
                              void* d_out, int out_size) {
    (void)in_sizes; (void)n_in; (void)out_size;
    const float* x      = (const float*)d_in[0];
    const float* attn_W = (const float*)d_in[1];
    const float* attn_b = (const float*)d_in[2];
    const float* comb_W = (const float*)d_in[3];
    const float* comb_b = (const float*)d_in[4];
    const float* w_ih   = (const float*)d_in[5];
    const float* w_hh   = (const float*)d_in[6];
    const float* b_ih   = (const float*)d_in[7];
    const float* b_hh   = (const float*)d_in[8];
    const float* out_W  = (const float*)d_in[9];
    const float* out_b  = (const float*)d_in[10];
    float* out = (float*)d_out;

    static bool attr_set = false;
    if (!attr_set) {
        cudaFuncSetAttribute(rnn_mma, cudaFuncAttributeMaxDynamicSharedMemorySize,
                             SMEM_TOTAL);
        attr_set = true;
    }

    k_prep<<<36096, 256>>>(x, attn_W, comb_W, w_ih, w_hh, out_W);
    rnn_mma<<<NCTA, NTHR, SMEM_TOTAL>>>(attn_b, comb_b, b_ih, b_hh, out_b, out);
}